// round 1
// baseline (speedup 1.0000x reference)
#include <cuda_runtime.h>
#include <math.h>

#define BB 32
#define NL 512
#define INDIM 1024
#define MEMD 1024

// ---------------- static scratch (no runtime allocation allowed) -------------
// ping-pong c/h buffers: max level size = B*NL*MEM floats = 64MB each
__device__ float g_c0[BB * NL * MEMD];
__device__ float g_h0[BB * NL * MEMD];
__device__ float g_c1[(BB * NL / 2) * MEMD];
__device__ float g_h1[(BB * NL / 2) * MEMD];
// GEMM output scratch: leaf needs B*NL*4*MEM floats = 256MB (largest user)
__device__ float g_scr[(size_t)BB * NL * 4 * MEMD];

// ---------------- generic fp32 GEMM: C[M,N] = A[M,K] * W[N,K]^T --------------
// BM=BN=128, BK=16, 256 threads, 8x8 accumulators per thread.
// N and K are always multiples of 128/16 here; M may be small (guarded).
#define BM 128
#define BN 128
#define BK 16

__global__ __launch_bounds__(256, 1)
void gemm_tn(const float* __restrict__ A, const float* __restrict__ W,
             float* __restrict__ C, int M, int N, int K) {
    __shared__ float As[BK][BM];
    __shared__ float Ws[BK][BN];

    const int tid = threadIdx.x;
    const int bm = blockIdx.y * BM;
    const int bn = blockIdx.x * BN;

    const int ty = tid >> 4;        // 0..15  (M dir)
    const int tx = tid & 15;        // 0..15  (N dir)
    const int m0 = ty * 8;
    const int n0 = tx * 8;

    float acc[8][8];
#pragma unroll
    for (int i = 0; i < 8; i++)
#pragma unroll
        for (int j = 0; j < 8; j++) acc[i][j] = 0.f;

    for (int k0 = 0; k0 < K; k0 += BK) {
        // cooperative loads: 512 float4 per operand tile, 2 per thread
#pragma unroll
        for (int v = 0; v < 2; v++) {
            int l4 = tid * 2 + v;
            int r  = l4 >> 2;            // row within tile (0..127)
            int kk = (l4 & 3) * 4;       // k offset within tile (0,4,8,12)
            float4 a;
            if (bm + r < M)
                a = *(const float4*)&A[(size_t)(bm + r) * K + k0 + kk];
            else
                a = make_float4(0.f, 0.f, 0.f, 0.f);
            As[kk + 0][r] = a.x; As[kk + 1][r] = a.y;
            As[kk + 2][r] = a.z; As[kk + 3][r] = a.w;
            float4 w = *(const float4*)&W[(size_t)(bn + r) * K + k0 + kk];
            Ws[kk + 0][r] = w.x; Ws[kk + 1][r] = w.y;
            Ws[kk + 2][r] = w.z; Ws[kk + 3][r] = w.w;
        }
        __syncthreads();

#pragma unroll
        for (int k = 0; k < BK; k++) {
            float4 a0 = *(const float4*)&As[k][m0];
            float4 a1 = *(const float4*)&As[k][m0 + 4];
            float4 w0 = *(const float4*)&Ws[k][n0];
            float4 w1 = *(const float4*)&Ws[k][n0 + 4];
            float a[8] = {a0.x, a0.y, a0.z, a0.w, a1.x, a1.y, a1.z, a1.w};
            float w[8] = {w0.x, w0.y, w0.z, w0.w, w1.x, w1.y, w1.z, w1.w};
#pragma unroll
            for (int i = 0; i < 8; i++)
#pragma unroll
                for (int j = 0; j < 8; j++)
                    acc[i][j] = fmaf(a[i], w[j], acc[i][j]);
        }
        __syncthreads();
    }

#pragma unroll
    for (int i = 0; i < 8; i++) {
        int r = bm + m0 + i;
        if (r < M) {
            float* crow = &C[(size_t)r * N + bn + n0];
            *(float4*)&crow[0] = make_float4(acc[i][0], acc[i][1], acc[i][2], acc[i][3]);
            *(float4*)&crow[4] = make_float4(acc[i][4], acc[i][5], acc[i][6], acc[i][7]);
        }
    }
}

// ---------------- elementwise gate kernels -----------------------------------
__device__ __forceinline__ float sigmoidf(float x) {
    return 1.f / (1.f + expf(-x));
}

// Leaf: children are zeros. g = inputs @ w_fioux^T, row stride 4*MEM (f,i,o,u).
__global__ void leaf_eltwise(const float* __restrict__ g,
                             const float* __restrict__ b,
                             float* __restrict__ c, float* __restrict__ h,
                             int rows) {
    int idx = blockIdx.x * blockDim.x + threadIdx.x;
    if (idx >= rows * MEMD) return;
    int row = idx / MEMD;
    int m   = idx - row * MEMD;
    const float* gr = g + (size_t)row * 4 * MEMD;
    float i = sigmoidf(gr[MEMD + m]     + b[MEMD + m]);
    float o = sigmoidf(gr[2 * MEMD + m] + b[2 * MEMD + m]);
    float u = tanhf   (gr[3 * MEMD + m] + b[3 * MEMD + m]);
    float cc = i * u;            // fc = f * 0
    c[idx] = cc;
    h[idx] = o * tanhf(cc);
}

// Internal node: x = 0 so fioux = b_fioux only.
// g1 = child_h @ w_iouh^T (row stride 3*MEM: ih,oh,uh)
// g2 = child_h @ w_fh^T   (row stride 2*MEM: fh_left, fh_right)
// c_prev viewed as [rows, 2*MEM] = [c_left || c_right]
__global__ void node_eltwise(const float* __restrict__ g1,
                             const float* __restrict__ g2,
                             const float* __restrict__ b,
                             const float* __restrict__ c_prev,
                             float* __restrict__ c, float* __restrict__ h,
                             int rows) {
    int idx = blockIdx.x * blockDim.x + threadIdx.x;
    if (idx >= rows * MEMD) return;
    int row = idx / MEMD;
    int m   = idx - row * MEMD;
    const float* g1r = g1 + (size_t)row * 3 * MEMD;
    const float* g2r = g2 + (size_t)row * 2 * MEMD;
    const float* cpr = c_prev + (size_t)row * 2 * MEMD;
    float i  = sigmoidf(g1r[m]            + b[MEMD + m]);
    float o  = sigmoidf(g1r[MEMD + m]     + b[2 * MEMD + m]);
    float u  = tanhf   (g1r[2 * MEMD + m] + b[3 * MEMD + m]);
    float fl = sigmoidf(g2r[m]        + b[m]);
    float fr = sigmoidf(g2r[MEMD + m] + b[m]);
    float cc = fmaf(i, u, fmaf(fl, cpr[m], fr * cpr[MEMD + m]));
    c[idx] = cc;
    h[idx] = o * tanhf(cc);
}

// ---------------- launch -----------------------------------------------------
extern "C" void kernel_launch(void* const* d_in, const int* in_sizes, int n_in,
                              void* d_out, int out_size) {
    const float* inputs  = (const float*)d_in[0];  // [B, NL, IN_DIM]
    const float* w_fioux = (const float*)d_in[1];  // [4M, IN_DIM]
    const float* b       = (const float*)d_in[2];  // [4M]
    const float* w_iouh  = (const float*)d_in[3];  // [3M, 2M]
    const float* w_fh    = (const float*)d_in[4];  // [2M, 2M]
    float* out = (float*)d_out;                    // [B, MEM]

    float *scr, *c0, *h0, *c1, *h1;
    cudaGetSymbolAddress((void**)&scr, g_scr);
    cudaGetSymbolAddress((void**)&c0, g_c0);
    cudaGetSymbolAddress((void**)&h0, g_h0);
    cudaGetSymbolAddress((void**)&c1, g_c1);
    cudaGetSymbolAddress((void**)&h1, g_h1);

    const int rowsL = BB * NL;  // 16384

    // Leaf level: one big GEMM + gates
    gemm_tn<<<dim3(4 * MEMD / BN, rowsL / BM), 256>>>(
        inputs, w_fioux, scr, rowsL, 4 * MEMD, INDIM);
    leaf_eltwise<<<(rowsL * MEMD + 255) / 256, 256>>>(scr, b, c0, h0, rowsL);

    float *cp = c0, *hp = h0, *cn = c1, *hn = h1;
    for (int n = NL / 2; n >= 1; n >>= 1) {
        int rows = BB * n;
        float* g1 = scr;                                  // [rows, 3M]
        float* g2 = scr + (size_t)rows * 3 * MEMD;        // [rows, 2M]
        // child_h = hp reinterpreted as [rows, 2M]
        gemm_tn<<<dim3(3 * MEMD / BN, (rows + BM - 1) / BM), 256>>>(
            hp, w_iouh, g1, rows, 3 * MEMD, 2 * MEMD);
        gemm_tn<<<dim3(2 * MEMD / BN, (rows + BM - 1) / BM), 256>>>(
            hp, w_fh, g2, rows, 2 * MEMD, 2 * MEMD);
        float* hout = (n == 1) ? out : hn;
        node_eltwise<<<(rows * MEMD + 255) / 256, 256>>>(
            g1, g2, b, cp, cn, hout, rows);
        // swap ping-pong
        float* t;
        t = cp; cp = cn; cn = t;
        t = hp; hp = hn; hn = t;
    }
}

// round 3
// speedup vs baseline: 2.6770x; 2.6770x over previous
#include <cuda_runtime.h>
#include <math.h>
#include <stdint.h>

#define BB 32
#define NL 512
#define INDIM 1024
#define MEMD 1024

// ---------------- static scratch (no runtime allocation allowed) -------------
__device__ float g_c0[BB * NL * MEMD];
__device__ float g_h0[BB * NL * MEMD];
__device__ float g_c1[(BB * NL / 2) * MEMD];
__device__ float g_h1[(BB * NL / 2) * MEMD];
// GEMM scratch: leaf 16384*3072, internal max 8192*5120
__device__ float g_scr[(size_t)BB * NL * 3 * MEMD];
// concatenated [w_iouh ; w_fh] : [5M, 2M]
__device__ float g_wcat[(size_t)5 * MEMD * 2 * MEMD];

// ============================================================================
// TF32 mma.sync GEMM: C[M,N] = A[M,K] * W[N,K]^T  (both K-major fp32)
// BM=BN=128, BK=32. 256 thr = 8 warps (2x4); warp tile 64x32 (4x4 m16n8k8).
// Smem [row][36] pad: conflict-free fragment gather + 16B-aligned cp.async.
// ============================================================================
#define BM 128
#define BN 128
#define BK 32
#define LDS_PAD 36                       // floats per smem row
#define TILE_F (128 * LDS_PAD)           // floats per A or B tile
#define STAGE_F (2 * TILE_F)
#define SMEM_DYN (2 * STAGE_F * 4)       // bytes, 2 stages

static __device__ __forceinline__ uint32_t smem_u32(const void* p) {
    uint32_t a;
    asm("{ .reg .u64 t; cvta.to.shared.u64 t, %1; cvt.u32.u64 %0, t; }"
        : "=r"(a) : "l"(p));
    return a;
}

static __device__ __forceinline__ void load_tile_pair(
    const float* __restrict__ A, const float* __restrict__ W,
    int M, int K, int bm, int bn, int k0, float* sA, int tid) {
    float* sB = sA + TILE_F;
    uint32_t uA = smem_u32(sA);
    uint32_t uB = smem_u32(sB);
#pragma unroll
    for (int i = 0; i < 4; i++) {
        int l = tid * 4 + i;            // 0..1023
        int r = l >> 3;                 // row 0..127
        int kc = l & 7;                 // 16B chunk 0..7
        uint32_t so = (uint32_t)(r * LDS_PAD + kc * 4) * 4;
        int arow = bm + r;
        int ok = (arow < M);
        const float* ga = A + (size_t)(ok ? arow : 0) * K + k0 + kc * 4;
        int sz = ok ? 16 : 0;
        asm volatile("cp.async.cg.shared.global [%0], [%1], 16, %2;\n"
                     :: "r"(uA + so), "l"(ga), "r"(sz));
        const float* gw = W + (size_t)(bn + r) * K + k0 + kc * 4;
        asm volatile("cp.async.cg.shared.global [%0], [%1], 16;\n"
                     :: "r"(uB + so), "l"(gw));
    }
}

__global__ __launch_bounds__(256)
void gemm_tc(const float* __restrict__ A, const float* __restrict__ W,
             float* __restrict__ C, int M, int N, int K) {
    extern __shared__ float smem[];

    const int tid = threadIdx.x;
    const int wid = tid >> 5;
    const int lane = tid & 31;
    const int gid = lane >> 2;          // 0..7
    const int tig = lane & 3;           // 0..3
    const int warp_m = wid >> 2;        // 0..1 -> m offset *64
    const int warp_n = wid & 3;         // 0..3 -> n offset *32
    const int bm = blockIdx.y * BM;
    const int bn = blockIdx.x * BN;
    const int nch = K / BK;

    float acc[4][4][4];
#pragma unroll
    for (int mt = 0; mt < 4; mt++)
#pragma unroll
        for (int nt = 0; nt < 4; nt++)
#pragma unroll
            for (int e = 0; e < 4; e++) acc[mt][nt][e] = 0.f;

    // prologue
    load_tile_pair(A, W, M, K, bm, bn, 0, smem, tid);
    asm volatile("cp.async.commit_group;\n");

    for (int it = 0; it < nch; it++) {
        float* buf = smem + (it & 1) * STAGE_F;
        if (it + 1 < nch) {
            load_tile_pair(A, W, M, K, bm, bn, (it + 1) * BK,
                           smem + ((it + 1) & 1) * STAGE_F, tid);
            asm volatile("cp.async.commit_group;\n");
            asm volatile("cp.async.wait_group 1;\n");
        } else {
            asm volatile("cp.async.wait_group 0;\n");
        }
        __syncthreads();

        const float* As = buf;
        const float* Bs = buf + TILE_F;
        const float* Arow0 = As + (warp_m * 64 + gid) * LDS_PAD;
        const float* Brow0 = Bs + (warp_n * 32 + gid) * LDS_PAD;

#pragma unroll
        for (int kk = 0; kk < 4; kk++) {
            const int k = kk * 8;
            uint32_t a[4][4], b[4][2];
#pragma unroll
            for (int mt = 0; mt < 4; mt++) {
                const float* r0 = Arow0 + mt * 16 * LDS_PAD;
                const float* r1 = r0 + 8 * LDS_PAD;
                a[mt][0] = __float_as_uint(r0[k + tig]);
                a[mt][1] = __float_as_uint(r1[k + tig]);
                a[mt][2] = __float_as_uint(r0[k + tig + 4]);
                a[mt][3] = __float_as_uint(r1[k + tig + 4]);
            }
#pragma unroll
            for (int nt = 0; nt < 4; nt++) {
                const float* r0 = Brow0 + nt * 8 * LDS_PAD;
                b[nt][0] = __float_as_uint(r0[k + tig]);
                b[nt][1] = __float_as_uint(r0[k + tig + 4]);
            }
#pragma unroll
            for (int mt = 0; mt < 4; mt++)
#pragma unroll
                for (int nt = 0; nt < 4; nt++) {
                    float* d = acc[mt][nt];
                    asm volatile(
                        "mma.sync.aligned.m16n8k8.row.col.f32.tf32.tf32.f32 "
                        "{%0,%1,%2,%3}, {%4,%5,%6,%7}, {%8,%9}, {%0,%1,%2,%3};"
                        : "+f"(d[0]), "+f"(d[1]), "+f"(d[2]), "+f"(d[3])
                        : "r"(a[mt][0]), "r"(a[mt][1]), "r"(a[mt][2]), "r"(a[mt][3]),
                          "r"(b[nt][0]), "r"(b[nt][1]));
                }
        }
        __syncthreads();
    }

    // epilogue: c0,c1 -> (row gid, col tig*2..+1); c2,c3 -> row gid+8
#pragma unroll
    for (int mt = 0; mt < 4; mt++) {
        int row0 = bm + warp_m * 64 + mt * 16 + gid;
        int row1 = row0 + 8;
#pragma unroll
        for (int nt = 0; nt < 4; nt++) {
            int col = bn + warp_n * 32 + nt * 8 + tig * 2;
            if (row0 < M)
                *(float2*)&C[(size_t)row0 * N + col] =
                    make_float2(acc[mt][nt][0], acc[mt][nt][1]);
            if (row1 < M)
                *(float2*)&C[(size_t)row1 * N + col] =
                    make_float2(acc[mt][nt][2], acc[mt][nt][3]);
        }
    }
}

// ---------------- elementwise gate kernels -----------------------------------
static __device__ __forceinline__ float sigmoidf_(float x) {
    return 1.f / (1.f + expf(-x));
}

// Leaf: children zero. g rows = [i | o | u], stride 3*MEM.
__global__ void leaf_eltwise(const float* __restrict__ g,
                             const float* __restrict__ b,
                             float* __restrict__ c, float* __restrict__ h,
                             int rows) {
    int idx = blockIdx.x * blockDim.x + threadIdx.x;
    if (idx >= rows * MEMD) return;
    int row = idx / MEMD;
    int m = idx - row * MEMD;
    const float* gr = g + (size_t)row * 3 * MEMD;
    float i = sigmoidf_(gr[m] + b[MEMD + m]);
    float o = sigmoidf_(gr[MEMD + m] + b[2 * MEMD + m]);
    float u = tanhf(gr[2 * MEMD + m] + b[3 * MEMD + m]);
    float cc = i * u;
    c[idx] = cc;
    h[idx] = o * tanhf(cc);
}

// Internal: x=0 => fioux = bias. g rows = [ih | oh | uh | fl | fr], stride 5*MEM.
__global__ void node_eltwise(const float* __restrict__ g,
                             const float* __restrict__ b,
                             const float* __restrict__ c_prev,
                             float* __restrict__ c, float* __restrict__ h,
                             int rows) {
    int idx = blockIdx.x * blockDim.x + threadIdx.x;
    if (idx >= rows * MEMD) return;
    int row = idx / MEMD;
    int m = idx - row * MEMD;
    const float* gr = g + (size_t)row * 5 * MEMD;
    const float* cpr = c_prev + (size_t)row * 2 * MEMD;
    float i = sigmoidf_(gr[m] + b[MEMD + m]);
    float o = sigmoidf_(gr[MEMD + m] + b[2 * MEMD + m]);
    float u = tanhf(gr[2 * MEMD + m] + b[3 * MEMD + m]);
    float fl = sigmoidf_(gr[3 * MEMD + m] + b[m]);
    float fr = sigmoidf_(gr[4 * MEMD + m] + b[m]);
    float cc = fmaf(i, u, fmaf(fl, cpr[m], fr * cpr[MEMD + m]));
    c[idx] = cc;
    h[idx] = o * tanhf(cc);
}

// ---------------- launch -----------------------------------------------------
extern "C" void kernel_launch(void* const* d_in, const int* in_sizes, int n_in,
                              void* d_out, int out_size) {
    const float* inputs  = (const float*)d_in[0];  // [B, NL, IN_DIM]
    const float* w_fioux = (const float*)d_in[1];  // [4M, IN_DIM]
    const float* b       = (const float*)d_in[2];  // [4M]
    const float* w_iouh  = (const float*)d_in[3];  // [3M, 2M]
    const float* w_fh    = (const float*)d_in[4];  // [2M, 2M]
    float* out = (float*)d_out;                    // [B, MEM]

    float *scr, *c0, *h0, *c1, *h1, *wcat;
    cudaGetSymbolAddress((void**)&scr, g_scr);
    cudaGetSymbolAddress((void**)&c0, g_c0);
    cudaGetSymbolAddress((void**)&h0, g_h0);
    cudaGetSymbolAddress((void**)&c1, g_c1);
    cudaGetSymbolAddress((void**)&h1, g_h1);
    cudaGetSymbolAddress((void**)&wcat, g_wcat);

    cudaFuncSetAttribute(gemm_tc, cudaFuncAttributeMaxDynamicSharedMemorySize,
                         SMEM_DYN);

    // wcat = [w_iouh ; w_fh]  (D2D async, capture-safe)
    cudaMemcpyAsync(wcat, w_iouh, (size_t)3 * MEMD * 2 * MEMD * sizeof(float),
                    cudaMemcpyDeviceToDevice);
    cudaMemcpyAsync(wcat + (size_t)3 * MEMD * 2 * MEMD, w_fh,
                    (size_t)2 * MEMD * 2 * MEMD * sizeof(float),
                    cudaMemcpyDeviceToDevice);

    const int rowsL = BB * NL;  // 16384

    // Leaf: inputs @ w_fioux[M:4M]^T   (skip dead f-block)
    gemm_tc<<<dim3(3 * MEMD / BN, rowsL / BM), 256, SMEM_DYN>>>(
        inputs, w_fioux + (size_t)MEMD * INDIM, scr, rowsL, 3 * MEMD, INDIM);
    leaf_eltwise<<<(rowsL * MEMD + 255) / 256, 256>>>(scr, b, c0, h0, rowsL);

    float *cp = c0, *hp = h0, *cn = c1, *hn = h1;
    for (int n = NL / 2; n >= 1; n >>= 1) {
        int rows = BB * n;
        // g = child_h @ wcat^T : [rows, 5M]
        gemm_tc<<<dim3(5 * MEMD / BN, (rows + BM - 1) / BM), 256, SMEM_DYN>>>(
            hp, wcat, scr, rows, 5 * MEMD, 2 * MEMD);
        float* hout = (n == 1) ? out : hn;
        node_eltwise<<<(rows * MEMD + 255) / 256, 256>>>(scr, b, cp, cn, hout, rows);
        float* t;
        t = cp; cp = cn; cn = t;
        t = hp; hp = hn; hn = t;
    }
}

// round 4
// speedup vs baseline: 2.9428x; 1.0993x over previous
#include <cuda_runtime.h>
#include <cuda_bf16.h>
#include <math.h>
#include <stdint.h>

#define BB 32
#define NL 512
#define INDIM 1024
#define MEMD 1024

typedef __nv_bfloat16 bf16;

// ---------------- static scratch (no runtime allocation allowed) -------------
__device__ __align__(256) float g_c0[BB * NL * MEMD];
__device__ __align__(256) float g_c1[(BB * NL / 2) * MEMD];
__device__ __align__(256) bf16 g_h0hi[BB * NL * MEMD];
__device__ __align__(256) bf16 g_h0lo[BB * NL * MEMD];
__device__ __align__(256) bf16 g_h1hi[(BB * NL / 2) * MEMD];
__device__ __align__(256) bf16 g_h1lo[(BB * NL / 2) * MEMD];
__device__ __align__(256) bf16 g_xhi[(size_t)BB * NL * INDIM];
__device__ __align__(256) bf16 g_xlo[(size_t)BB * NL * INDIM];
__device__ __align__(256) bf16 g_wxhi[(size_t)3 * MEMD * INDIM];
__device__ __align__(256) bf16 g_wxlo[(size_t)3 * MEMD * INDIM];
__device__ __align__(256) bf16 g_wchi[(size_t)5 * MEMD * 2 * MEMD];
__device__ __align__(256) bf16 g_wclo[(size_t)5 * MEMD * 2 * MEMD];
__device__ __align__(256) float g_scr[(size_t)BB * NL * 3 * MEMD];

// ---------------- fp32 -> bf16 hi/lo split (vectorized x4) -------------------
__global__ void split_k(const float* __restrict__ s, bf16* __restrict__ hi,
                        bf16* __restrict__ lo, int n4) {
    int i = blockIdx.x * blockDim.x + threadIdx.x;
    if (i >= n4) return;
    float4 v = ((const float4*)s)[i];
    bf16 h0 = __float2bfloat16(v.x), h1 = __float2bfloat16(v.y);
    bf16 h2 = __float2bfloat16(v.z), h3 = __float2bfloat16(v.w);
    bf16 l0 = __float2bfloat16(v.x - __bfloat162float(h0));
    bf16 l1 = __float2bfloat16(v.y - __bfloat162float(h1));
    bf16 l2 = __float2bfloat16(v.z - __bfloat162float(h2));
    bf16 l3 = __float2bfloat16(v.w - __bfloat162float(h3));
    ((__nv_bfloat162*)hi)[i * 2]     = __nv_bfloat162(h0, h1);
    ((__nv_bfloat162*)hi)[i * 2 + 1] = __nv_bfloat162(h2, h3);
    ((__nv_bfloat162*)lo)[i * 2]     = __nv_bfloat162(l0, l1);
    ((__nv_bfloat162*)lo)[i * 2 + 1] = __nv_bfloat162(l2, l3);
}

// ============================================================================
// split-bf16 GEMM: C[M,N] = (Ahi+Alo)[M,K] * (Whi+Wlo)[N,K]^T  (K-major)
// BM=BN=128, BK=32. 8 warps (2x4): warp tile 64x32 = 4x4 m16n8k16 x 3 splits.
// ldmatrix.x4 fragment loads; smem rows padded to 80B (conflict-free).
// ============================================================================
#define BM 128
#define BN 128
#define BK 32
#define SROW 80
#define PLANE_B (128 * SROW)
#define STAGE_B (4 * PLANE_B)
#define NSTG 3
#define SMEM_DYN (NSTG * STAGE_B)

static __device__ __forceinline__ uint32_t smem_u32(const void* p) {
    uint32_t a;
    asm("{ .reg .u64 t; cvta.to.shared.u64 t, %1; cvt.u32.u64 %0, t; }"
        : "=r"(a) : "l"(p));
    return a;
}

#define LDM4(r0, r1, r2, r3, addr)                                            \
    asm volatile("ldmatrix.sync.aligned.m8n8.x4.shared.b16 {%0,%1,%2,%3}, [%4];" \
                 : "=r"(r0), "=r"(r1), "=r"(r2), "=r"(r3) : "r"(addr))

#define MMA_BF16(d, a, b)                                                     \
    asm volatile("mma.sync.aligned.m16n8k16.row.col.f32.bf16.bf16.f32 "       \
                 "{%0,%1,%2,%3},{%4,%5,%6,%7},{%8,%9},{%0,%1,%2,%3};"         \
                 : "+f"(d[0]), "+f"(d[1]), "+f"(d[2]), "+f"(d[3])             \
                 : "r"(a[0]), "r"(a[1]), "r"(a[2]), "r"(a[3]),                \
                   "r"(b[0]), "r"(b[1]))

static __device__ __forceinline__ void load_stage(
    const bf16* __restrict__ Ahi, const bf16* __restrict__ Alo,
    const bf16* __restrict__ Whi, const bf16* __restrict__ Wlo,
    int M, int K, int bm, int bn, int k0, uint32_t sbase, int tid) {
#pragma unroll
    for (int i = 0; i < 8; i++) {
        int l = tid + 256 * i;          // 0..2047
        int plane = l >> 9;             // 0:Ahi 1:Alo 2:Whi 3:Wlo
        int c = l & 511;
        int row = c >> 2;
        int ch = c & 3;
        uint32_t dst = sbase + plane * PLANE_B + row * SROW + ch * 16;
        if (plane < 2) {
            const bf16* base = plane ? Alo : Ahi;
            int gr = bm + row;
            int ok = gr < M;
            const bf16* g = base + (size_t)(ok ? gr : 0) * K + k0 + ch * 8;
            int sz = ok ? 16 : 0;
            asm volatile("cp.async.cg.shared.global [%0], [%1], 16, %2;\n"
                         :: "r"(dst), "l"(g), "r"(sz));
        } else {
            const bf16* base = (plane == 2) ? Whi : Wlo;
            const bf16* g = base + (size_t)(bn + row) * K + k0 + ch * 8;
            asm volatile("cp.async.cg.shared.global [%0], [%1], 16;\n"
                         :: "r"(dst), "l"(g));
        }
    }
}

__global__ __launch_bounds__(256, 1)
void gemm_split(const bf16* __restrict__ Ahi, const bf16* __restrict__ Alo,
                const bf16* __restrict__ Whi, const bf16* __restrict__ Wlo,
                float* __restrict__ C, int M, int N, int K) {
    extern __shared__ char smem_raw[];
    const uint32_t sbase = smem_u32(smem_raw);

    const int tid = threadIdx.x;
    const int wid = tid >> 5;
    const int lane = tid & 31;
    const int warp_m = wid >> 2;        // 0..1 (*64)
    const int warp_n = wid & 3;         // 0..3 (*32)
    const int bm = blockIdx.y * BM;
    const int bn = blockIdx.x * BN;
    const int nch = K / BK;

    // lane-invariant components of ldmatrix addresses (byte offsets in plane)
    const uint32_t a_base =
        (uint32_t)(warp_m * 64 + ((lane >> 3) & 1) * 8 + (lane & 7)) * SROW +
        ((lane >> 4) & 1) * 16;                          // koff 8 elems = 16B
    const uint32_t b_base =
        (uint32_t)(warp_n * 32 + ((lane >> 4) & 1) * 8 + (lane & 7)) * SROW +
        ((lane >> 3) & 1) * 16;

    float acc[4][4][4];
#pragma unroll
    for (int mt = 0; mt < 4; mt++)
#pragma unroll
        for (int nt = 0; nt < 4; nt++)
#pragma unroll
            for (int e = 0; e < 4; e++) acc[mt][nt][e] = 0.f;

    load_stage(Ahi, Alo, Whi, Wlo, M, K, bm, bn, 0, sbase, tid);
    asm volatile("cp.async.commit_group;\n");
    load_stage(Ahi, Alo, Whi, Wlo, M, K, bm, bn, BK, sbase + STAGE_B, tid);
    asm volatile("cp.async.commit_group;\n");

    for (int it = 0; it < nch; it++) {
        asm volatile("cp.async.wait_group 1;\n");
        __syncthreads();

        int nl = it + 2;
        if (nl < nch)
            load_stage(Ahi, Alo, Whi, Wlo, M, K, bm, bn, nl * BK,
                       sbase + (nl % NSTG) * STAGE_B, tid);
        asm volatile("cp.async.commit_group;\n");

        const uint32_t sb = sbase + (it % NSTG) * STAGE_B;
        const uint32_t pAhi = sb;
        const uint32_t pAlo = sb + PLANE_B;
        const uint32_t pBhi = sb + 2 * PLANE_B;
        const uint32_t pBlo = sb + 3 * PLANE_B;

#pragma unroll
        for (int ks = 0; ks < 2; ks++) {
            const uint32_t kb = ks * 32;     // 16 elems = 32B
            uint32_t bhi[4][2], blo[4][2];
#pragma unroll
            for (int q = 0; q < 2; q++) {
                uint32_t ad = pBhi + b_base + q * 16 * SROW + kb;
                LDM4(bhi[2 * q][0], bhi[2 * q][1], bhi[2 * q + 1][0],
                     bhi[2 * q + 1][1], ad);
                ad = pBlo + b_base + q * 16 * SROW + kb;
                LDM4(blo[2 * q][0], blo[2 * q][1], blo[2 * q + 1][0],
                     blo[2 * q + 1][1], ad);
            }
#pragma unroll
            for (int mt = 0; mt < 4; mt++) {
                uint32_t ahi[4], alo[4];
                uint32_t ad = pAhi + a_base + mt * 16 * SROW + kb;
                LDM4(ahi[0], ahi[1], ahi[2], ahi[3], ad);
                ad = pAlo + a_base + mt * 16 * SROW + kb;
                LDM4(alo[0], alo[1], alo[2], alo[3], ad);
#pragma unroll
                for (int nt = 0; nt < 4; nt++) {
                    MMA_BF16(acc[mt][nt], ahi, bhi[nt]);
                    MMA_BF16(acc[mt][nt], ahi, blo[nt]);
                    MMA_BF16(acc[mt][nt], alo, bhi[nt]);
                }
            }
        }
    }

    const int gid = lane >> 2;
    const int tig = lane & 3;
#pragma unroll
    for (int mt = 0; mt < 4; mt++) {
        int row0 = bm + warp_m * 64 + mt * 16 + gid;
        int row1 = row0 + 8;
#pragma unroll
        for (int nt = 0; nt < 4; nt++) {
            int col = bn + warp_n * 32 + nt * 8 + tig * 2;
            if (row0 < M)
                *(float2*)&C[(size_t)row0 * N + col] =
                    make_float2(acc[mt][nt][0], acc[mt][nt][1]);
            if (row1 < M)
                *(float2*)&C[(size_t)row1 * N + col] =
                    make_float2(acc[mt][nt][2], acc[mt][nt][3]);
        }
    }
}

// ---------------- elementwise gate kernels -----------------------------------
static __device__ __forceinline__ float sigmoidf_(float x) {
    return 1.f / (1.f + expf(-x));
}

// Leaf: children zero. g rows = [i | o | u], stride 3*MEM. h -> bf16 planes.
__global__ void leaf_eltwise(const float* __restrict__ g,
                             const float* __restrict__ b,
                             float* __restrict__ c,
                             bf16* __restrict__ hhi, bf16* __restrict__ hlo,
                             int rows) {
    int idx = blockIdx.x * blockDim.x + threadIdx.x;
    if (idx >= rows * MEMD) return;
    int row = idx / MEMD;
    int m = idx - row * MEMD;
    const float* gr = g + (size_t)row * 3 * MEMD;
    float i = sigmoidf_(gr[m] + b[MEMD + m]);
    float o = sigmoidf_(gr[MEMD + m] + b[2 * MEMD + m]);
    float u = tanhf(gr[2 * MEMD + m] + b[3 * MEMD + m]);
    float cc = i * u;
    c[idx] = cc;
    float hh = o * tanhf(cc);
    bf16 hb = __float2bfloat16(hh);
    hhi[idx] = hb;
    hlo[idx] = __float2bfloat16(hh - __bfloat162float(hb));
}

// Internal: x=0 => fioux = bias. g rows = [ih | oh | uh | fl | fr], stride 5*MEM.
__global__ void node_eltwise(const float* __restrict__ g,
                             const float* __restrict__ b,
                             const float* __restrict__ c_prev,
                             float* __restrict__ c,
                             bf16* __restrict__ hhi, bf16* __restrict__ hlo,
                             float* __restrict__ hroot,   // non-null at root
                             int rows) {
    int idx = blockIdx.x * blockDim.x + threadIdx.x;
    if (idx >= rows * MEMD) return;
    int row = idx / MEMD;
    int m = idx - row * MEMD;
    const float* gr = g + (size_t)row * 5 * MEMD;
    const float* cpr = c_prev + (size_t)row * 2 * MEMD;
    float i = sigmoidf_(gr[m] + b[MEMD + m]);
    float o = sigmoidf_(gr[MEMD + m] + b[2 * MEMD + m]);
    float u = tanhf(gr[2 * MEMD + m] + b[3 * MEMD + m]);
    float fl = sigmoidf_(gr[3 * MEMD + m] + b[m]);
    float fr = sigmoidf_(gr[4 * MEMD + m] + b[m]);
    float cc = fmaf(i, u, fmaf(fl, cpr[m], fr * cpr[MEMD + m]));
    c[idx] = cc;
    float hh = o * tanhf(cc);
    if (hroot) {
        hroot[idx] = hh;
    } else {
        bf16 hb = __float2bfloat16(hh);
        hhi[idx] = hb;
        hlo[idx] = __float2bfloat16(hh - __bfloat162float(hb));
    }
}

// ---------------- launch -----------------------------------------------------
extern "C" void kernel_launch(void* const* d_in, const int* in_sizes, int n_in,
                              void* d_out, int out_size) {
    const float* inputs  = (const float*)d_in[0];  // [B, NL, IN_DIM]
    const float* w_fioux = (const float*)d_in[1];  // [4M, IN_DIM]
    const float* b       = (const float*)d_in[2];  // [4M]
    const float* w_iouh  = (const float*)d_in[3];  // [3M, 2M]
    const float* w_fh    = (const float*)d_in[4];  // [2M, 2M]
    float* out = (float*)d_out;                    // [B, MEM]

    float *scr, *c0, *c1;
    bf16 *h0hi, *h0lo, *h1hi, *h1lo, *xhi, *xlo, *wxhi, *wxlo, *wchi, *wclo;
    cudaGetSymbolAddress((void**)&scr, g_scr);
    cudaGetSymbolAddress((void**)&c0, g_c0);
    cudaGetSymbolAddress((void**)&c1, g_c1);
    cudaGetSymbolAddress((void**)&h0hi, g_h0hi);
    cudaGetSymbolAddress((void**)&h0lo, g_h0lo);
    cudaGetSymbolAddress((void**)&h1hi, g_h1hi);
    cudaGetSymbolAddress((void**)&h1lo, g_h1lo);
    cudaGetSymbolAddress((void**)&xhi, g_xhi);
    cudaGetSymbolAddress((void**)&xlo, g_xlo);
    cudaGetSymbolAddress((void**)&wxhi, g_wxhi);
    cudaGetSymbolAddress((void**)&wxlo, g_wxlo);
    cudaGetSymbolAddress((void**)&wchi, g_wchi);
    cudaGetSymbolAddress((void**)&wclo, g_wclo);

    cudaFuncSetAttribute(gemm_split, cudaFuncAttributeMaxDynamicSharedMemorySize,
                         SMEM_DYN);

    const int rowsL = BB * NL;  // 16384

    // split conversions (every replay; ~60us total)
    {
        int n4;
        n4 = rowsL * INDIM / 4;
        split_k<<<(n4 + 255) / 256, 256>>>(inputs, xhi, xlo, n4);
        n4 = 3 * MEMD * INDIM / 4;
        split_k<<<(n4 + 255) / 256, 256>>>(w_fioux + (size_t)MEMD * INDIM,
                                           wxhi, wxlo, n4);
        n4 = 3 * MEMD * 2 * MEMD / 4;
        split_k<<<(n4 + 255) / 256, 256>>>(w_iouh, wchi, wclo, n4);
        size_t off = (size_t)3 * MEMD * 2 * MEMD;
        n4 = 2 * MEMD * 2 * MEMD / 4;
        split_k<<<(n4 + 255) / 256, 256>>>(w_fh, wchi + off, wclo + off, n4);
    }

    // Leaf: x @ w_fioux[M:4M]^T  -> scr [rowsL, 3M]
    gemm_split<<<dim3(3 * MEMD / BN, rowsL / BM), 256, SMEM_DYN>>>(
        xhi, xlo, wxhi, wxlo, scr, rowsL, 3 * MEMD, INDIM);
    leaf_eltwise<<<(rowsL * MEMD + 255) / 256, 256>>>(scr, b, c0, h0hi, h0lo,
                                                      rowsL);

    float *cp = c0, *cn = c1;
    bf16 *hpi = h0hi, *hpl = h0lo, *hni = h1hi, *hnl = h1lo;
    for (int n = NL / 2; n >= 1; n >>= 1) {
        int rows = BB * n;
        // g = child_h @ [w_iouh;w_fh]^T : [rows, 5M]; child_h = h planes [rows, 2M]
        gemm_split<<<dim3(5 * MEMD / BN, (rows + BM - 1) / BM), 256, SMEM_DYN>>>(
            hpi, hpl, wchi, wclo, scr, rows, 5 * MEMD, 2 * MEMD);
        node_eltwise<<<(rows * MEMD + 255) / 256, 256>>>(
            scr, b, cp, cn, hni, hnl, (n == 1) ? out : (float*)nullptr, rows);
        float* tc = cp; cp = cn; cn = tc;
        bf16* t;
        t = hpi; hpi = hni; hni = t;
        t = hpl; hpl = hnl; hnl = t;
    }
}

// round 5
// speedup vs baseline: 3.4872x; 1.1850x over previous
#include <cuda_runtime.h>
#include <cuda_bf16.h>
#include <math.h>
#include <stdint.h>

#define BB 32
#define NL 512
#define INDIM 1024
#define MEMD 1024

typedef __nv_bfloat16 bf16;

// ---------------- static scratch (no runtime allocation allowed) -------------
__device__ __align__(256) float g_c0[BB * NL * MEMD];
__device__ __align__(256) float g_c1[(BB * NL / 2) * MEMD];
__device__ __align__(256) bf16 g_h0hi[BB * NL * MEMD];
__device__ __align__(256) bf16 g_h0lo[BB * NL * MEMD];
__device__ __align__(256) bf16 g_h1hi[(BB * NL / 2) * MEMD];
__device__ __align__(256) bf16 g_h1lo[(BB * NL / 2) * MEMD];
__device__ __align__(256) bf16 g_xhi[(size_t)BB * NL * INDIM];
__device__ __align__(256) bf16 g_xlo[(size_t)BB * NL * INDIM];
__device__ __align__(256) bf16 g_wxhi[(size_t)3 * MEMD * INDIM];
__device__ __align__(256) bf16 g_wxlo[(size_t)3 * MEMD * INDIM];
__device__ __align__(256) bf16 g_wchi[(size_t)5 * MEMD * 2 * MEMD];
__device__ __align__(256) bf16 g_wclo[(size_t)5 * MEMD * 2 * MEMD];
__device__ __align__(256) float g_scr[(size_t)BB * NL * 3 * MEMD];

// ---------------- fp32 -> bf16 hi/lo split (vectorized x4) -------------------
__global__ void split_k(const float* __restrict__ s, bf16* __restrict__ hi,
                        bf16* __restrict__ lo, int n4) {
    int i = blockIdx.x * blockDim.x + threadIdx.x;
    if (i >= n4) return;
    float4 v = ((const float4*)s)[i];
    bf16 h0 = __float2bfloat16(v.x), h1 = __float2bfloat16(v.y);
    bf16 h2 = __float2bfloat16(v.z), h3 = __float2bfloat16(v.w);
    bf16 l0 = __float2bfloat16(v.x - __bfloat162float(h0));
    bf16 l1 = __float2bfloat16(v.y - __bfloat162float(h1));
    bf16 l2 = __float2bfloat16(v.z - __bfloat162float(h2));
    bf16 l3 = __float2bfloat16(v.w - __bfloat162float(h3));
    ((__nv_bfloat162*)hi)[i * 2]     = __nv_bfloat162(h0, h1);
    ((__nv_bfloat162*)hi)[i * 2 + 1] = __nv_bfloat162(h2, h3);
    ((__nv_bfloat162*)lo)[i * 2]     = __nv_bfloat162(l0, l1);
    ((__nv_bfloat162*)lo)[i * 2 + 1] = __nv_bfloat162(l2, l3);
}

// ============================================================================
// split-bf16 GEMM: C[M,N] = (Ahi+Alo)[M,K] * (Whi+Wlo)[N,K]^T  (K-major)
// BM=BN=128, BK=32. 8 warps (2x4): warp tile 64x32 = 4x4 m16n8k16 x 3 splits.
// 2-stage cp.async (80KB) -> 2 CTAs/SM for latency hiding.
// ============================================================================
#define BM 128
#define BN 128
#define BK 32
#define SROW 80
#define PLANE_B (128 * SROW)
#define STAGE_B (4 * PLANE_B)
#define NSTG 2
#define SMEM_DYN (NSTG * STAGE_B)

static __device__ __forceinline__ uint32_t smem_u32(const void* p) {
    uint32_t a;
    asm("{ .reg .u64 t; cvta.to.shared.u64 t, %1; cvt.u32.u64 %0, t; }"
        : "=r"(a) : "l"(p));
    return a;
}

#define LDM4(r0, r1, r2, r3, addr)                                            \
    asm volatile("ldmatrix.sync.aligned.m8n8.x4.shared.b16 {%0,%1,%2,%3}, [%4];" \
                 : "=r"(r0), "=r"(r1), "=r"(r2), "=r"(r3) : "r"(addr))

#define MMA_BF16(d, a, b)                                                     \
    asm volatile("mma.sync.aligned.m16n8k16.row.col.f32.bf16.bf16.f32 "       \
                 "{%0,%1,%2,%3},{%4,%5,%6,%7},{%8,%9},{%0,%1,%2,%3};"         \
                 : "+f"(d[0]), "+f"(d[1]), "+f"(d[2]), "+f"(d[3])             \
                 : "r"(a[0]), "r"(a[1]), "r"(a[2]), "r"(a[3]),                \
                   "r"(b[0]), "r"(b[1]))

static __device__ __forceinline__ void load_stage(
    const bf16* __restrict__ Ahi, const bf16* __restrict__ Alo,
    const bf16* __restrict__ Whi, const bf16* __restrict__ Wlo,
    int M, int K, int bm, int bn, int k0, uint32_t sbase, int tid) {
#pragma unroll
    for (int i = 0; i < 8; i++) {
        int l = tid + 256 * i;          // 0..2047
        int plane = l >> 9;             // 0:Ahi 1:Alo 2:Whi 3:Wlo
        int c = l & 511;
        int row = c >> 2;
        int ch = c & 3;
        uint32_t dst = sbase + plane * PLANE_B + row * SROW + ch * 16;
        if (plane < 2) {
            const bf16* base = plane ? Alo : Ahi;
            int gr = bm + row;
            int ok = gr < M;
            const bf16* g = base + (size_t)(ok ? gr : 0) * K + k0 + ch * 8;
            int sz = ok ? 16 : 0;
            asm volatile("cp.async.cg.shared.global [%0], [%1], 16, %2;\n"
                         :: "r"(dst), "l"(g), "r"(sz));
        } else {
            const bf16* base = (plane == 2) ? Whi : Wlo;
            const bf16* g = base + (size_t)(bn + row) * K + k0 + ch * 8;
            asm volatile("cp.async.cg.shared.global [%0], [%1], 16;\n"
                         :: "r"(dst), "l"(g));
        }
    }
}

__global__ __launch_bounds__(256, 2)
void gemm_split(const bf16* __restrict__ Ahi, const bf16* __restrict__ Alo,
                const bf16* __restrict__ Whi, const bf16* __restrict__ Wlo,
                float* __restrict__ C, int M, int N, int K) {
    extern __shared__ char smem_raw[];
    const uint32_t sbase = smem_u32(smem_raw);

    const int tid = threadIdx.x;
    const int wid = tid >> 5;
    const int lane = tid & 31;
    const int warp_m = wid >> 2;        // 0..1 (*64)
    const int warp_n = wid & 3;         // 0..3 (*32)
    const int bm = blockIdx.y * BM;
    const int bn = blockIdx.x * BN;
    const int nch = K / BK;

    const uint32_t a_base =
        (uint32_t)(warp_m * 64 + ((lane >> 3) & 1) * 8 + (lane & 7)) * SROW +
        ((lane >> 4) & 1) * 16;
    const uint32_t b_base =
        (uint32_t)(warp_n * 32 + ((lane >> 4) & 1) * 8 + (lane & 7)) * SROW +
        ((lane >> 3) & 1) * 16;

    float acc[4][4][4];
#pragma unroll
    for (int mt = 0; mt < 4; mt++)
#pragma unroll
        for (int nt = 0; nt < 4; nt++)
#pragma unroll
            for (int e = 0; e < 4; e++) acc[mt][nt][e] = 0.f;

    load_stage(Ahi, Alo, Whi, Wlo, M, K, bm, bn, 0, sbase, tid);
    asm volatile("cp.async.commit_group;\n");

    for (int it = 0; it < nch; it++) {
        if (it + 1 < nch) {
            load_stage(Ahi, Alo, Whi, Wlo, M, K, bm, bn, (it + 1) * BK,
                       sbase + ((it + 1) & 1) * STAGE_B, tid);
            asm volatile("cp.async.commit_group;\n");
            asm volatile("cp.async.wait_group 1;\n");
        } else {
            asm volatile("cp.async.wait_group 0;\n");
        }
        __syncthreads();

        const uint32_t sb = sbase + (it & 1) * STAGE_B;
        const uint32_t pAhi = sb;
        const uint32_t pAlo = sb + PLANE_B;
        const uint32_t pBhi = sb + 2 * PLANE_B;
        const uint32_t pBlo = sb + 3 * PLANE_B;

#pragma unroll
        for (int ks = 0; ks < 2; ks++) {
            const uint32_t kb = ks * 32;     // 16 elems = 32B
            uint32_t bhi[4][2], blo[4][2];
#pragma unroll
            for (int q = 0; q < 2; q++) {
                uint32_t ad = pBhi + b_base + q * 16 * SROW + kb;
                LDM4(bhi[2 * q][0], bhi[2 * q][1], bhi[2 * q + 1][0],
                     bhi[2 * q + 1][1], ad);
                ad = pBlo + b_base + q * 16 * SROW + kb;
                LDM4(blo[2 * q][0], blo[2 * q][1], blo[2 * q + 1][0],
                     blo[2 * q + 1][1], ad);
            }
#pragma unroll
            for (int mt = 0; mt < 4; mt++) {
                uint32_t ahi[4], alo[4];
                uint32_t ad = pAhi + a_base + mt * 16 * SROW + kb;
                LDM4(ahi[0], ahi[1], ahi[2], ahi[3], ad);
                ad = pAlo + a_base + mt * 16 * SROW + kb;
                LDM4(alo[0], alo[1], alo[2], alo[3], ad);
#pragma unroll
                for (int nt = 0; nt < 4; nt++) {
                    MMA_BF16(acc[mt][nt], ahi, bhi[nt]);
                    MMA_BF16(acc[mt][nt], ahi, blo[nt]);
                    MMA_BF16(acc[mt][nt], alo, bhi[nt]);
                }
            }
        }
        __syncthreads();
    }

    const int gid = lane >> 2;
    const int tig = lane & 3;
#pragma unroll
    for (int mt = 0; mt < 4; mt++) {
        int row0 = bm + warp_m * 64 + mt * 16 + gid;
        int row1 = row0 + 8;
#pragma unroll
        for (int nt = 0; nt < 4; nt++) {
            int col = bn + warp_n * 32 + nt * 8 + tig * 2;
            if (row0 < M)
                *(float2*)&C[(size_t)row0 * N + col] =
                    make_float2(acc[mt][nt][0], acc[mt][nt][1]);
            if (row1 < M)
                *(float2*)&C[(size_t)row1 * N + col] =
                    make_float2(acc[mt][nt][2], acc[mt][nt][3]);
        }
    }
}

// ---------------- elementwise gate kernels (float4 vectorized) ---------------
static __device__ __forceinline__ float sigmoidf_(float x) {
    return 1.f / (1.f + expf(-x));
}
static __device__ __forceinline__ void split_store(bf16* hhi, bf16* hlo,
                                                   int i4, float4 h) {
    bf16 h0 = __float2bfloat16(h.x), h1 = __float2bfloat16(h.y);
    bf16 h2 = __float2bfloat16(h.z), h3 = __float2bfloat16(h.w);
    ((__nv_bfloat162*)hhi)[i4 * 2]     = __nv_bfloat162(h0, h1);
    ((__nv_bfloat162*)hhi)[i4 * 2 + 1] = __nv_bfloat162(h2, h3);
    ((__nv_bfloat162*)hlo)[i4 * 2] = __nv_bfloat162(
        __float2bfloat16(h.x - __bfloat162float(h0)),
        __float2bfloat16(h.y - __bfloat162float(h1)));
    ((__nv_bfloat162*)hlo)[i4 * 2 + 1] = __nv_bfloat162(
        __float2bfloat16(h.z - __bfloat162float(h2)),
        __float2bfloat16(h.w - __bfloat162float(h3)));
}

// Leaf: children zero. g rows = [i | o | u], stride 3*MEM.
__global__ void leaf_eltwise(const float* __restrict__ g,
                             const float* __restrict__ b,
                             float* __restrict__ c,
                             bf16* __restrict__ hhi, bf16* __restrict__ hlo,
                             int rows) {
    int i4 = blockIdx.x * blockDim.x + threadIdx.x;
    if (i4 >= rows * (MEMD / 4)) return;
    int row = i4 / (MEMD / 4);
    int m = (i4 - row * (MEMD / 4)) * 4;
    const float* gr = g + (size_t)row * 3 * MEMD;
    float4 gi = *(const float4*)&gr[m];
    float4 go = *(const float4*)&gr[MEMD + m];
    float4 gu = *(const float4*)&gr[2 * MEMD + m];
    float4 bi = *(const float4*)&b[MEMD + m];
    float4 bo = *(const float4*)&b[2 * MEMD + m];
    float4 bu = *(const float4*)&b[3 * MEMD + m];
    float4 cc, hh;
    {
        float iv = sigmoidf_(gi.x + bi.x), ov = sigmoidf_(go.x + bo.x);
        float uv = tanhf(gu.x + bu.x);
        cc.x = iv * uv; hh.x = ov * tanhf(cc.x);
        iv = sigmoidf_(gi.y + bi.y); ov = sigmoidf_(go.y + bo.y);
        uv = tanhf(gu.y + bu.y);
        cc.y = iv * uv; hh.y = ov * tanhf(cc.y);
        iv = sigmoidf_(gi.z + bi.z); ov = sigmoidf_(go.z + bo.z);
        uv = tanhf(gu.z + bu.z);
        cc.z = iv * uv; hh.z = ov * tanhf(cc.z);
        iv = sigmoidf_(gi.w + bi.w); ov = sigmoidf_(go.w + bo.w);
        uv = tanhf(gu.w + bu.w);
        cc.w = iv * uv; hh.w = ov * tanhf(cc.w);
    }
    ((float4*)c)[i4] = cc;
    split_store(hhi, hlo, i4, hh);
}

// Internal: x=0 => fioux = bias. g rows = [ih | oh | uh | fl | fr], stride 5*MEM.
__global__ void node_eltwise(const float* __restrict__ g,
                             const float* __restrict__ b,
                             const float* __restrict__ c_prev,
                             float* __restrict__ c,
                             bf16* __restrict__ hhi, bf16* __restrict__ hlo,
                             float* __restrict__ hroot, int rows) {
    int i4 = blockIdx.x * blockDim.x + threadIdx.x;
    if (i4 >= rows * (MEMD / 4)) return;
    int row = i4 / (MEMD / 4);
    int m = (i4 - row * (MEMD / 4)) * 4;
    const float* gr = g + (size_t)row * 5 * MEMD;
    const float* cpr = c_prev + (size_t)row * 2 * MEMD;
    float4 gi = *(const float4*)&gr[m];
    float4 go = *(const float4*)&gr[MEMD + m];
    float4 gu = *(const float4*)&gr[2 * MEMD + m];
    float4 gfl = *(const float4*)&gr[3 * MEMD + m];
    float4 gfr = *(const float4*)&gr[4 * MEMD + m];
    float4 bi = *(const float4*)&b[MEMD + m];
    float4 bo = *(const float4*)&b[2 * MEMD + m];
    float4 bu = *(const float4*)&b[3 * MEMD + m];
    float4 bf = *(const float4*)&b[m];
    float4 cl = *(const float4*)&cpr[m];
    float4 cr = *(const float4*)&cpr[MEMD + m];
    float4 cc, hh;
#define NODE1(X)                                                              \
    {                                                                         \
        float iv = sigmoidf_(gi.X + bi.X), ov = sigmoidf_(go.X + bo.X);       \
        float uv = tanhf(gu.X + bu.X);                                        \
        float fl = sigmoidf_(gfl.X + bf.X), fr = sigmoidf_(gfr.X + bf.X);     \
        cc.X = fmaf(iv, uv, fmaf(fl, cl.X, fr * cr.X));                       \
        hh.X = ov * tanhf(cc.X);                                              \
    }
    NODE1(x) NODE1(y) NODE1(z) NODE1(w)
#undef NODE1
    ((float4*)c)[i4] = cc;
    if (hroot)
        ((float4*)hroot)[i4] = hh;
    else
        split_store(hhi, hlo, i4, hh);
}

// ---------------- launch -----------------------------------------------------
extern "C" void kernel_launch(void* const* d_in, const int* in_sizes, int n_in,
                              void* d_out, int out_size) {
    const float* inputs  = (const float*)d_in[0];
    const float* w_fioux = (const float*)d_in[1];
    const float* b       = (const float*)d_in[2];
    const float* w_iouh  = (const float*)d_in[3];
    const float* w_fh    = (const float*)d_in[4];
    float* out = (float*)d_out;

    float *scr, *c0, *c1;
    bf16 *h0hi, *h0lo, *h1hi, *h1lo, *xhi, *xlo, *wxhi, *wxlo, *wchi, *wclo;
    cudaGetSymbolAddress((void**)&scr, g_scr);
    cudaGetSymbolAddress((void**)&c0, g_c0);
    cudaGetSymbolAddress((void**)&c1, g_c1);
    cudaGetSymbolAddress((void**)&h0hi, g_h0hi);
    cudaGetSymbolAddress((void**)&h0lo, g_h0lo);
    cudaGetSymbolAddress((void**)&h1hi, g_h1hi);
    cudaGetSymbolAddress((void**)&h1lo, g_h1lo);
    cudaGetSymbolAddress((void**)&xhi, g_xhi);
    cudaGetSymbolAddress((void**)&xlo, g_xlo);
    cudaGetSymbolAddress((void**)&wxhi, g_wxhi);
    cudaGetSymbolAddress((void**)&wxlo, g_wxlo);
    cudaGetSymbolAddress((void**)&wchi, g_wchi);
    cudaGetSymbolAddress((void**)&wclo, g_wclo);

    cudaFuncSetAttribute(gemm_split, cudaFuncAttributeMaxDynamicSharedMemorySize,
                         SMEM_DYN);

    const int rowsL = BB * NL;  // 16384

    {
        int n4;
        n4 = rowsL * INDIM / 4;
        split_k<<<(n4 + 255) / 256, 256>>>(inputs, xhi, xlo, n4);
        n4 = 3 * MEMD * INDIM / 4;
        split_k<<<(n4 + 255) / 256, 256>>>(w_fioux + (size_t)MEMD * INDIM,
                                           wxhi, wxlo, n4);
        n4 = 3 * MEMD * 2 * MEMD / 4;
        split_k<<<(n4 + 255) / 256, 256>>>(w_iouh, wchi, wclo, n4);
        size_t off = (size_t)3 * MEMD * 2 * MEMD;
        n4 = 2 * MEMD * 2 * MEMD / 4;
        split_k<<<(n4 + 255) / 256, 256>>>(w_fh, wchi + off, wclo + off, n4);
    }

    gemm_split<<<dim3(3 * MEMD / BN, rowsL / BM), 256, SMEM_DYN>>>(
        xhi, xlo, wxhi, wxlo, scr, rowsL, 3 * MEMD, INDIM);
    leaf_eltwise<<<(rowsL * MEMD / 4 + 255) / 256, 256>>>(scr, b, c0, h0hi,
                                                          h0lo, rowsL);

    float *cp = c0, *cn = c1;
    bf16 *hpi = h0hi, *hpl = h0lo, *hni = h1hi, *hnl = h1lo;
    for (int n = NL / 2; n >= 1; n >>= 1) {
        int rows = BB * n;
        gemm_split<<<dim3(5 * MEMD / BN, (rows + BM - 1) / BM), 256, SMEM_DYN>>>(
            hpi, hpl, wchi, wclo, scr, rows, 5 * MEMD, 2 * MEMD);
        node_eltwise<<<(rows * MEMD / 4 + 255) / 256, 256>>>(
            scr, b, cp, cn, hni, hnl, (n == 1) ? out : (float*)nullptr, rows);
        float* tc = cp; cp = cn; cn = tc;
        bf16* t;
        t = hpi; hpi = hni; hni = t;
        t = hpl; hpl = hnl; hnl = t;
    }
}

// round 6
// speedup vs baseline: 3.6375x; 1.0431x over previous
#include <cuda_runtime.h>
#include <cuda_bf16.h>
#include <math.h>
#include <stdint.h>

#define BB 32
#define NL 512
#define INDIM 1024
#define MEMD 1024

typedef __nv_bfloat16 bf16;

// ---------------- static scratch (no runtime allocation allowed) -------------
__device__ __align__(256) float g_c0[BB * NL * MEMD];
__device__ __align__(256) float g_c1[(BB * NL / 2) * MEMD];
__device__ __align__(256) bf16 g_h0hi[BB * NL * MEMD];
__device__ __align__(256) bf16 g_h0lo[BB * NL * MEMD];
__device__ __align__(256) bf16 g_h1hi[(BB * NL / 2) * MEMD];
__device__ __align__(256) bf16 g_h1lo[(BB * NL / 2) * MEMD];
__device__ __align__(256) bf16 g_xhi[(size_t)BB * NL * INDIM];
__device__ __align__(256) bf16 g_xlo[(size_t)BB * NL * INDIM];
__device__ __align__(256) bf16 g_wxhi[(size_t)3 * MEMD * INDIM];
__device__ __align__(256) bf16 g_wxlo[(size_t)3 * MEMD * INDIM];
__device__ __align__(256) bf16 g_wchi[(size_t)5 * MEMD * 2 * MEMD];
__device__ __align__(256) bf16 g_wclo[(size_t)5 * MEMD * 2 * MEMD];
__device__ __align__(256) float g_scr[(size_t)BB * NL * 3 * MEMD];

// ---------------- fused fp32 -> bf16 hi/lo split (4 segments, 1 launch) ------
__global__ void split_all(const float* __restrict__ s0, bf16* h0, bf16* l0, int n0,
                          const float* __restrict__ s1, bf16* h1, bf16* l1, int n1,
                          const float* __restrict__ s2, bf16* h2, bf16* l2, int n2,
                          const float* __restrict__ s3, bf16* h3, bf16* l3, int n3) {
    int i = blockIdx.x * blockDim.x + threadIdx.x;
    const float* s;
    bf16 *hi, *lo;
    int j = i;
    if (j < n0) { s = s0; hi = h0; lo = l0; }
    else {
        j -= n0;
        if (j < n1) { s = s1; hi = h1; lo = l1; }
        else {
            j -= n1;
            if (j < n2) { s = s2; hi = h2; lo = l2; }
            else {
                j -= n2;
                if (j >= n3) return;
                s = s3; hi = h3; lo = l3;
            }
        }
    }
    float4 v = ((const float4*)s)[j];
    bf16 a0 = __float2bfloat16(v.x), a1 = __float2bfloat16(v.y);
    bf16 a2 = __float2bfloat16(v.z), a3 = __float2bfloat16(v.w);
    ((__nv_bfloat162*)hi)[j * 2]     = __nv_bfloat162(a0, a1);
    ((__nv_bfloat162*)hi)[j * 2 + 1] = __nv_bfloat162(a2, a3);
    ((__nv_bfloat162*)lo)[j * 2] = __nv_bfloat162(
        __float2bfloat16(v.x - __bfloat162float(a0)),
        __float2bfloat16(v.y - __bfloat162float(a1)));
    ((__nv_bfloat162*)lo)[j * 2 + 1] = __nv_bfloat162(
        __float2bfloat16(v.z - __bfloat162float(a2)),
        __float2bfloat16(v.w - __bfloat162float(a3)));
}

// ============================================================================
// split-bf16 GEMM: C[M,N] = (Ahi+Alo)[M,K] * (Whi+Wlo)[N,K]^T  (K-major)
// BM=BN=128, BK=32. 8 warps (2x4): warp tile 64x32 = 4x4 m16n8k16 x 3 splits.
// 2-stage cp.async (80KB) -> 2 CTAs/SM. gridDim.z = deterministic K-slices:
// slice z handles kcps chunks starting at z*kcps, writes C + z*M*N.
// ============================================================================
#define BM 128
#define BN 128
#define BK 32
#define SROW 80
#define PLANE_B (128 * SROW)
#define STAGE_B (4 * PLANE_B)
#define SMEM_DYN (2 * STAGE_B)

static __device__ __forceinline__ uint32_t smem_u32(const void* p) {
    uint32_t a;
    asm("{ .reg .u64 t; cvta.to.shared.u64 t, %1; cvt.u32.u64 %0, t; }"
        : "=r"(a) : "l"(p));
    return a;
}

#define LDM4(r0, r1, r2, r3, addr)                                            \
    asm volatile("ldmatrix.sync.aligned.m8n8.x4.shared.b16 {%0,%1,%2,%3}, [%4];" \
                 : "=r"(r0), "=r"(r1), "=r"(r2), "=r"(r3) : "r"(addr))

#define MMA_BF16(d, a, b)                                                     \
    asm volatile("mma.sync.aligned.m16n8k16.row.col.f32.bf16.bf16.f32 "       \
                 "{%0,%1,%2,%3},{%4,%5,%6,%7},{%8,%9},{%0,%1,%2,%3};"         \
                 : "+f"(d[0]), "+f"(d[1]), "+f"(d[2]), "+f"(d[3])             \
                 : "r"(a[0]), "r"(a[1]), "r"(a[2]), "r"(a[3]),                \
                   "r"(b[0]), "r"(b[1]))

static __device__ __forceinline__ void load_stage(
    const bf16* __restrict__ Ahi, const bf16* __restrict__ Alo,
    const bf16* __restrict__ Whi, const bf16* __restrict__ Wlo,
    int M, int K, int bm, int bn, int k0, uint32_t sbase, int tid) {
#pragma unroll
    for (int i = 0; i < 8; i++) {
        int l = tid + 256 * i;          // 0..2047
        int plane = l >> 9;             // 0:Ahi 1:Alo 2:Whi 3:Wlo
        int c = l & 511;
        int row = c >> 2;
        int ch = c & 3;
        uint32_t dst = sbase + plane * PLANE_B + row * SROW + ch * 16;
        if (plane < 2) {
            const bf16* base = plane ? Alo : Ahi;
            int gr = bm + row;
            int ok = gr < M;
            const bf16* g = base + (size_t)(ok ? gr : 0) * K + k0 + ch * 8;
            int sz = ok ? 16 : 0;
            asm volatile("cp.async.cg.shared.global [%0], [%1], 16, %2;\n"
                         :: "r"(dst), "l"(g), "r"(sz));
        } else {
            const bf16* base = (plane == 2) ? Whi : Wlo;
            const bf16* g = base + (size_t)(bn + row) * K + k0 + ch * 8;
            asm volatile("cp.async.cg.shared.global [%0], [%1], 16;\n"
                         :: "r"(dst), "l"(g));
        }
    }
}

__global__ __launch_bounds__(256, 2)
void gemm_split(const bf16* __restrict__ Ahi, const bf16* __restrict__ Alo,
                const bf16* __restrict__ Whi, const bf16* __restrict__ Wlo,
                float* __restrict__ C, int M, int N, int K, int kcps) {
    extern __shared__ char smem_raw[];
    const uint32_t sbase = smem_u32(smem_raw);

    const int tid = threadIdx.x;
    const int wid = tid >> 5;
    const int lane = tid & 31;
    const int warp_m = wid >> 2;
    const int warp_n = wid & 3;
    const int bm = blockIdx.y * BM;
    const int bn = blockIdx.x * BN;
    const int kbase = blockIdx.z * kcps * BK;
    C += (size_t)blockIdx.z * M * N;    // partial slice

    const uint32_t a_base =
        (uint32_t)(warp_m * 64 + ((lane >> 3) & 1) * 8 + (lane & 7)) * SROW +
        ((lane >> 4) & 1) * 16;
    const uint32_t b_base =
        (uint32_t)(warp_n * 32 + ((lane >> 4) & 1) * 8 + (lane & 7)) * SROW +
        ((lane >> 3) & 1) * 16;

    float acc[4][4][4];
#pragma unroll
    for (int mt = 0; mt < 4; mt++)
#pragma unroll
        for (int nt = 0; nt < 4; nt++)
#pragma unroll
            for (int e = 0; e < 4; e++) acc[mt][nt][e] = 0.f;

    load_stage(Ahi, Alo, Whi, Wlo, M, K, bm, bn, kbase, sbase, tid);
    asm volatile("cp.async.commit_group;\n");

    for (int it = 0; it < kcps; it++) {
        if (it + 1 < kcps) {
            load_stage(Ahi, Alo, Whi, Wlo, M, K, bm, bn, kbase + (it + 1) * BK,
                       sbase + ((it + 1) & 1) * STAGE_B, tid);
            asm volatile("cp.async.commit_group;\n");
            asm volatile("cp.async.wait_group 1;\n");
        } else {
            asm volatile("cp.async.wait_group 0;\n");
        }
        __syncthreads();

        const uint32_t sb = sbase + (it & 1) * STAGE_B;
        const uint32_t pAhi = sb;
        const uint32_t pAlo = sb + PLANE_B;
        const uint32_t pBhi = sb + 2 * PLANE_B;
        const uint32_t pBlo = sb + 3 * PLANE_B;

#pragma unroll
        for (int ks = 0; ks < 2; ks++) {
            const uint32_t kb = ks * 32;
            uint32_t bhi[4][2], blo[4][2];
#pragma unroll
            for (int q = 0; q < 2; q++) {
                uint32_t ad = pBhi + b_base + q * 16 * SROW + kb;
                LDM4(bhi[2 * q][0], bhi[2 * q][1], bhi[2 * q + 1][0],
                     bhi[2 * q + 1][1], ad);
                ad = pBlo + b_base + q * 16 * SROW + kb;
                LDM4(blo[2 * q][0], blo[2 * q][1], blo[2 * q + 1][0],
                     blo[2 * q + 1][1], ad);
            }
#pragma unroll
            for (int mt = 0; mt < 4; mt++) {
                uint32_t ahi[4], alo[4];
                uint32_t ad = pAhi + a_base + mt * 16 * SROW + kb;
                LDM4(ahi[0], ahi[1], ahi[2], ahi[3], ad);
                ad = pAlo + a_base + mt * 16 * SROW + kb;
                LDM4(alo[0], alo[1], alo[2], alo[3], ad);
#pragma unroll
                for (int nt = 0; nt < 4; nt++) {
                    MMA_BF16(acc[mt][nt], ahi, bhi[nt]);
                    MMA_BF16(acc[mt][nt], ahi, blo[nt]);
                    MMA_BF16(acc[mt][nt], alo, bhi[nt]);
                }
            }
        }
        __syncthreads();
    }

    const int gid = lane >> 2;
    const int tig = lane & 3;
#pragma unroll
    for (int mt = 0; mt < 4; mt++) {
        int row0 = bm + warp_m * 64 + mt * 16 + gid;
        int row1 = row0 + 8;
#pragma unroll
        for (int nt = 0; nt < 4; nt++) {
            int col = bn + warp_n * 32 + nt * 8 + tig * 2;
            if (row0 < M)
                *(float2*)&C[(size_t)row0 * N + col] =
                    make_float2(acc[mt][nt][0], acc[mt][nt][1]);
            if (row1 < M)
                *(float2*)&C[(size_t)row1 * N + col] =
                    make_float2(acc[mt][nt][2], acc[mt][nt][3]);
        }
    }
}

// ---------------- elementwise gate kernels (float4 vectorized) ---------------
static __device__ __forceinline__ float sigmoidf_(float x) {
    return 1.f / (1.f + expf(-x));
}
static __device__ __forceinline__ void split_store(bf16* hhi, bf16* hlo,
                                                   int i4, float4 h) {
    bf16 h0 = __float2bfloat16(h.x), h1 = __float2bfloat16(h.y);
    bf16 h2 = __float2bfloat16(h.z), h3 = __float2bfloat16(h.w);
    ((__nv_bfloat162*)hhi)[i4 * 2]     = __nv_bfloat162(h0, h1);
    ((__nv_bfloat162*)hhi)[i4 * 2 + 1] = __nv_bfloat162(h2, h3);
    ((__nv_bfloat162*)hlo)[i4 * 2] = __nv_bfloat162(
        __float2bfloat16(h.x - __bfloat162float(h0)),
        __float2bfloat16(h.y - __bfloat162float(h1)));
    ((__nv_bfloat162*)hlo)[i4 * 2 + 1] = __nv_bfloat162(
        __float2bfloat16(h.z - __bfloat162float(h2)),
        __float2bfloat16(h.w - __bfloat162float(h3)));
}

__global__ void leaf_eltwise(const float* __restrict__ g,
                             const float* __restrict__ b,
                             float* __restrict__ c,
                             bf16* __restrict__ hhi, bf16* __restrict__ hlo,
                             int rows) {
    int i4 = blockIdx.x * blockDim.x + threadIdx.x;
    if (i4 >= rows * (MEMD / 4)) return;
    int row = i4 / (MEMD / 4);
    int m = (i4 - row * (MEMD / 4)) * 4;
    const float* gr = g + (size_t)row * 3 * MEMD;
    float4 gi = *(const float4*)&gr[m];
    float4 go = *(const float4*)&gr[MEMD + m];
    float4 gu = *(const float4*)&gr[2 * MEMD + m];
    float4 bi = *(const float4*)&b[MEMD + m];
    float4 bo = *(const float4*)&b[2 * MEMD + m];
    float4 bu = *(const float4*)&b[3 * MEMD + m];
    float4 cc, hh;
#define LEAF1(X)                                                              \
    {                                                                         \
        float iv = sigmoidf_(gi.X + bi.X), ov = sigmoidf_(go.X + bo.X);       \
        float uv = tanhf(gu.X + bu.X);                                        \
        cc.X = iv * uv; hh.X = ov * tanhf(cc.X);                              \
    }
    LEAF1(x) LEAF1(y) LEAF1(z) LEAF1(w)
#undef LEAF1
    ((float4*)c)[i4] = cc;
    split_store(hhi, hlo, i4, hh);
}

// Internal: x=0 => fioux = bias. g slices: nsl partial GEMM outputs to sum.
__global__ void node_eltwise(const float* __restrict__ g,
                             const float* __restrict__ b,
                             const float* __restrict__ c_prev,
                             float* __restrict__ c,
                             bf16* __restrict__ hhi, bf16* __restrict__ hlo,
                             float* __restrict__ hroot, int rows, int nsl) {
    int i4 = blockIdx.x * blockDim.x + threadIdx.x;
    if (i4 >= rows * (MEMD / 4)) return;
    int row = i4 / (MEMD / 4);
    int m = (i4 - row * (MEMD / 4)) * 4;
    const size_t sstride = (size_t)rows * 5 * MEMD;
    const float* gr = g + (size_t)row * 5 * MEMD;
    float4 gi = *(const float4*)&gr[m];
    float4 go = *(const float4*)&gr[MEMD + m];
    float4 gu = *(const float4*)&gr[2 * MEMD + m];
    float4 gfl = *(const float4*)&gr[3 * MEMD + m];
    float4 gfr = *(const float4*)&gr[4 * MEMD + m];
    for (int s = 1; s < nsl; s++) {
        const float* gs = gr + s * sstride;
        float4 t;
        t = *(const float4*)&gs[m];
        gi.x += t.x; gi.y += t.y; gi.z += t.z; gi.w += t.w;
        t = *(const float4*)&gs[MEMD + m];
        go.x += t.x; go.y += t.y; go.z += t.z; go.w += t.w;
        t = *(const float4*)&gs[2 * MEMD + m];
        gu.x += t.x; gu.y += t.y; gu.z += t.z; gu.w += t.w;
        t = *(const float4*)&gs[3 * MEMD + m];
        gfl.x += t.x; gfl.y += t.y; gfl.z += t.z; gfl.w += t.w;
        t = *(const float4*)&gs[4 * MEMD + m];
        gfr.x += t.x; gfr.y += t.y; gfr.z += t.z; gfr.w += t.w;
    }
    const float* cpr = c_prev + (size_t)row * 2 * MEMD;
    float4 bi = *(const float4*)&b[MEMD + m];
    float4 bo = *(const float4*)&b[2 * MEMD + m];
    float4 bu = *(const float4*)&b[3 * MEMD + m];
    float4 bf = *(const float4*)&b[m];
    float4 cl = *(const float4*)&cpr[m];
    float4 cr = *(const float4*)&cpr[MEMD + m];
    float4 cc, hh;
#define NODE1(X)                                                              \
    {                                                                         \
        float iv = sigmoidf_(gi.X + bi.X), ov = sigmoidf_(go.X + bo.X);       \
        float uv = tanhf(gu.X + bu.X);                                        \
        float fl = sigmoidf_(gfl.X + bf.X), fr = sigmoidf_(gfr.X + bf.X);     \
        cc.X = fmaf(iv, uv, fmaf(fl, cl.X, fr * cr.X));                       \
        hh.X = ov * tanhf(cc.X);                                              \
    }
    NODE1(x) NODE1(y) NODE1(z) NODE1(w)
#undef NODE1
    ((float4*)c)[i4] = cc;
    if (hroot)
        ((float4*)hroot)[i4] = hh;
    else
        split_store(hhi, hlo, i4, hh);
}

// ---------------- launch -----------------------------------------------------
extern "C" void kernel_launch(void* const* d_in, const int* in_sizes, int n_in,
                              void* d_out, int out_size) {
    const float* inputs  = (const float*)d_in[0];
    const float* w_fioux = (const float*)d_in[1];
    const float* b       = (const float*)d_in[2];
    const float* w_iouh  = (const float*)d_in[3];
    const float* w_fh    = (const float*)d_in[4];
    float* out = (float*)d_out;

    float *scr, *c0, *c1;
    bf16 *h0hi, *h0lo, *h1hi, *h1lo, *xhi, *xlo, *wxhi, *wxlo, *wchi, *wclo;
    cudaGetSymbolAddress((void**)&scr, g_scr);
    cudaGetSymbolAddress((void**)&c0, g_c0);
    cudaGetSymbolAddress((void**)&c1, g_c1);
    cudaGetSymbolAddress((void**)&h0hi, g_h0hi);
    cudaGetSymbolAddress((void**)&h0lo, g_h0lo);
    cudaGetSymbolAddress((void**)&h1hi, g_h1hi);
    cudaGetSymbolAddress((void**)&h1lo, g_h1lo);
    cudaGetSymbolAddress((void**)&xhi, g_xhi);
    cudaGetSymbolAddress((void**)&xlo, g_xlo);
    cudaGetSymbolAddress((void**)&wxhi, g_wxhi);
    cudaGetSymbolAddress((void**)&wxlo, g_wxlo);
    cudaGetSymbolAddress((void**)&wchi, g_wchi);
    cudaGetSymbolAddress((void**)&wclo, g_wclo);

    cudaFuncSetAttribute(gemm_split, cudaFuncAttributeMaxDynamicSharedMemorySize,
                         SMEM_DYN);

    const int rowsL = BB * NL;  // 16384

    // one fused split launch
    {
        int n0 = rowsL * INDIM / 4;
        int n1 = 3 * MEMD * INDIM / 4;
        int n2 = 3 * MEMD * 2 * MEMD / 4;
        int n3 = 2 * MEMD * 2 * MEMD / 4;
        size_t off = (size_t)3 * MEMD * 2 * MEMD;
        int tot = n0 + n1 + n2 + n3;
        split_all<<<(tot + 255) / 256, 256>>>(
            inputs, xhi, xlo, n0,
            w_fioux + (size_t)MEMD * INDIM, wxhi, wxlo, n1,
            w_iouh, wchi, wclo, n2,
            w_fh, wchi + off, wclo + off, n3);
    }

    gemm_split<<<dim3(3 * MEMD / BN, rowsL / BM, 1), 256, SMEM_DYN>>>(
        xhi, xlo, wxhi, wxlo, scr, rowsL, 3 * MEMD, INDIM, INDIM / BK);
    leaf_eltwise<<<(rowsL * MEMD / 4 + 255) / 256, 256>>>(scr, b, c0, h0hi,
                                                          h0lo, rowsL);

    float *cp = c0, *cn = c1;
    bf16 *hpi = h0hi, *hpl = h0lo, *hni = h1hi, *hnl = h1lo;
    for (int n = NL / 2; n >= 1; n >>= 1) {
        int rows = BB * n;
        int ks = rows >= 1024 ? 1 : rows == 512 ? 2 : rows == 256 ? 4 : 8;
        int kcps = (2 * MEMD / BK) / ks;   // 64 / ks
        int gy = (rows + BM - 1) / BM;
        gemm_split<<<dim3(5 * MEMD / BN, gy, ks), 256, SMEM_DYN>>>(
            hpi, hpl, wchi, wclo, scr, rows, 5 * MEMD, 2 * MEMD, kcps);
        node_eltwise<<<(rows * MEMD / 4 + 255) / 256, 256>>>(
            scr, b, cp, cn, hni, hnl, (n == 1) ? out : (float*)nullptr, rows, ks);
        float* tc = cp; cp = cn; cn = tc;
        bf16* t;
        t = hpi; hpi = hni; hni = t;
        t = hpl; hpl = hnl; hnl = t;
    }
}

// round 7
// speedup vs baseline: 4.1852x; 1.1506x over previous
#include <cuda_runtime.h>
#include <cuda_bf16.h>
#include <math.h>
#include <stdint.h>

#define BB 32
#define NL 512
#define INDIM 1024
#define MEMD 1024

typedef __nv_bfloat16 bf16;

// ---------------- static scratch (no runtime allocation allowed) -------------
__device__ __align__(256) float g_c0[BB * NL * MEMD];
__device__ __align__(256) float g_c1[(BB * NL / 2) * MEMD];
__device__ __align__(256) bf16 g_h0hi[BB * NL * MEMD];
__device__ __align__(256) bf16 g_h0lo[BB * NL * MEMD];
__device__ __align__(256) bf16 g_h1hi[(BB * NL / 2) * MEMD];
__device__ __align__(256) bf16 g_h1lo[(BB * NL / 2) * MEMD];
__device__ __align__(256) bf16 g_xhi[(size_t)BB * NL * INDIM];
__device__ __align__(256) bf16 g_xlo[(size_t)BB * NL * INDIM];
__device__ __align__(256) bf16 g_wxhi[(size_t)3 * MEMD * INDIM];
__device__ __align__(256) bf16 g_wxlo[(size_t)3 * MEMD * INDIM];
__device__ __align__(256) bf16 g_wchi[(size_t)5 * MEMD * 2 * MEMD];
__device__ __align__(256) bf16 g_wclo[(size_t)5 * MEMD * 2 * MEMD];
__device__ __align__(256) float g_scr[(size_t)BB * NL * 3 * MEMD];

// ---------------- fused fp32 -> bf16 hi/lo split (4 segments, 1 launch) ------
__global__ void split_all(const float* __restrict__ s0, bf16* h0, bf16* l0, int n0,
                          const float* __restrict__ s1, bf16* h1, bf16* l1, int n1,
                          const float* __restrict__ s2, bf16* h2, bf16* l2, int n2,
                          const float* __restrict__ s3, bf16* h3, bf16* l3, int n3) {
    int i = blockIdx.x * blockDim.x + threadIdx.x;
    const float* s;
    bf16 *hi, *lo;
    int j = i;
    if (j < n0) { s = s0; hi = h0; lo = l0; }
    else {
        j -= n0;
        if (j < n1) { s = s1; hi = h1; lo = l1; }
        else {
            j -= n1;
            if (j < n2) { s = s2; hi = h2; lo = l2; }
            else {
                j -= n2;
                if (j >= n3) return;
                s = s3; hi = h3; lo = l3;
            }
        }
    }
    float4 v = ((const float4*)s)[j];
    bf16 a0 = __float2bfloat16(v.x), a1 = __float2bfloat16(v.y);
    bf16 a2 = __float2bfloat16(v.z), a3 = __float2bfloat16(v.w);
    ((__nv_bfloat162*)hi)[j * 2]     = __nv_bfloat162(a0, a1);
    ((__nv_bfloat162*)hi)[j * 2 + 1] = __nv_bfloat162(a2, a3);
    ((__nv_bfloat162*)lo)[j * 2] = __nv_bfloat162(
        __float2bfloat16(v.x - __bfloat162float(a0)),
        __float2bfloat16(v.y - __bfloat162float(a1)));
    ((__nv_bfloat162*)lo)[j * 2 + 1] = __nv_bfloat162(
        __float2bfloat16(v.z - __bfloat162float(a2)),
        __float2bfloat16(v.w - __bfloat162float(a3)));
}

// ============================================================================
// split-bf16 GEMM: C[M,N] = (Ahi+Alo)[M,K] * (Whi+Wlo)[N,K]^T  (K-major)
// BM=BN=128, BK=32. 8 warps (2x4): warp tile 64x32 = 4x4 m16n8k16 x 3 splits.
// XOR-swizzled 64B smem rows (no pad): chunk' = chunk ^ ((row>>1)&3).
// 3-stage cp.async (96KB), ONE __syncthreads per chunk, 2 CTAs/SM.
// gridDim.z = deterministic K-slices writing disjoint partial outputs.
// ============================================================================
#define BM 128
#define BN 128
#define BK 32
#define PLANE_B 8192                 // 128 rows * 64B
#define STAGE_B (4 * PLANE_B)        // Ahi,Alo,Whi,Wlo
#define NSTG 3
#define SMEM_DYN (NSTG * STAGE_B + 128)

static __device__ __forceinline__ uint32_t smem_u32(const void* p) {
    uint32_t a;
    asm("{ .reg .u64 t; cvta.to.shared.u64 t, %1; cvt.u32.u64 %0, t; }"
        : "=r"(a) : "l"(p));
    return a;
}

#define LDM4(r0, r1, r2, r3, addr)                                            \
    asm volatile("ldmatrix.sync.aligned.m8n8.x4.shared.b16 {%0,%1,%2,%3}, [%4];" \
                 : "=r"(r0), "=r"(r1), "=r"(r2), "=r"(r3) : "r"(addr))

#define MMA_BF16(d, a, b)                                                     \
    asm volatile("mma.sync.aligned.m16n8k16.row.col.f32.bf16.bf16.f32 "       \
                 "{%0,%1,%2,%3},{%4,%5,%6,%7},{%8,%9},{%0,%1,%2,%3};"         \
                 : "+f"(d[0]), "+f"(d[1]), "+f"(d[2]), "+f"(d[3])             \
                 : "r"(a[0]), "r"(a[1]), "r"(a[2]), "r"(a[3]),                \
                   "r"(b[0]), "r"(b[1]))

static __device__ __forceinline__ void load_stage(
    const bf16* __restrict__ Ahi, const bf16* __restrict__ Alo,
    const bf16* __restrict__ Whi, const bf16* __restrict__ Wlo,
    int M, int K, int bm, int bn, int k0, uint32_t sbase, int tid) {
#pragma unroll
    for (int i = 0; i < 8; i++) {
        int l = tid + 256 * i;          // 0..2047
        int plane = l >> 9;             // 0:Ahi 1:Alo 2:Whi 3:Wlo
        int c = l & 511;
        int row = c >> 2;
        int ch = c & 3;
        int sc = ch ^ ((row >> 1) & 3);          // swizzled 16B chunk
        uint32_t dst = sbase + plane * PLANE_B + row * 64 + sc * 16;
        if (plane < 2) {
            const bf16* base = plane ? Alo : Ahi;
            int gr = bm + row;
            int ok = gr < M;
            const bf16* g = base + (size_t)(ok ? gr : 0) * K + k0 + ch * 8;
            int sz = ok ? 16 : 0;
            asm volatile("cp.async.cg.shared.global [%0], [%1], 16, %2;\n"
                         :: "r"(dst), "l"(g), "r"(sz));
        } else {
            const bf16* base = (plane == 2) ? Whi : Wlo;
            const bf16* g = base + (size_t)(bn + row) * K + k0 + ch * 8;
            asm volatile("cp.async.cg.shared.global [%0], [%1], 16;\n"
                         :: "r"(dst), "l"(g));
        }
    }
}

__global__ __launch_bounds__(256, 2)
void gemm_split(const bf16* __restrict__ Ahi, const bf16* __restrict__ Alo,
                const bf16* __restrict__ Whi, const bf16* __restrict__ Wlo,
                float* __restrict__ C, int M, int N, int K, int kcps) {
    extern __shared__ __align__(128) char smem_raw[];
    uint32_t sbase = smem_u32(smem_raw);
    sbase = (sbase + 127u) & ~127u;

    const int tid = threadIdx.x;
    const int wid = tid >> 5;
    const int lane = tid & 31;
    const int warp_m = wid >> 2;
    const int warp_n = wid & 3;
    const int bm = blockIdx.y * BM;
    const int bn = blockIdx.x * BN;
    const int kbase = blockIdx.z * kcps * BK;
    C += (size_t)blockIdx.z * M * N;    // partial slice

    // per-lane ldmatrix addressing (byte offsets within a plane)
    const int ra = ((lane >> 3) & 1) * 8 + (lane & 7);   // A row part 0..15
    const int cha = (lane >> 4) & 1;                     // A chunk part
    const int swza = (ra >> 1) & 3;
    const uint32_t a_row = (uint32_t)(warp_m * 64 + ra) * 64;
    const uint32_t ak0 = ((cha ^ swza) << 4);            // ks=0 chunk offset
    const uint32_t ak1 = (((2 + cha) ^ swza) << 4);      // ks=1

    const int rb = ((lane >> 4) & 1) * 8 + (lane & 7);   // B row part
    const int chb = (lane >> 3) & 1;
    const int swzb = (rb >> 1) & 3;
    const uint32_t b_row = (uint32_t)(warp_n * 32 + rb) * 64;
    const uint32_t bk0 = ((chb ^ swzb) << 4);
    const uint32_t bk1 = (((2 + chb) ^ swzb) << 4);

    float acc[4][4][4];
#pragma unroll
    for (int mt = 0; mt < 4; mt++)
#pragma unroll
        for (int nt = 0; nt < 4; nt++)
#pragma unroll
            for (int e = 0; e < 4; e++) acc[mt][nt][e] = 0.f;

    load_stage(Ahi, Alo, Whi, Wlo, M, K, bm, bn, kbase, sbase, tid);
    asm volatile("cp.async.commit_group;\n");
    if (1 < kcps)
        load_stage(Ahi, Alo, Whi, Wlo, M, K, bm, bn, kbase + BK,
                   sbase + STAGE_B, tid);
    asm volatile("cp.async.commit_group;\n");

    for (int it = 0; it < kcps; it++) {
        asm volatile("cp.async.wait_group 1;\n");
        __syncthreads();

        // prefetch chunk it+2 into stage (it+2)%3 (consumed at it-1; safe)
        if (it + 2 < kcps)
            load_stage(Ahi, Alo, Whi, Wlo, M, K, bm, bn, kbase + (it + 2) * BK,
                       sbase + ((it + 2) % NSTG) * STAGE_B, tid);
        asm volatile("cp.async.commit_group;\n");

        const uint32_t sb = sbase + (it % NSTG) * STAGE_B;
        const uint32_t pAhi = sb;
        const uint32_t pAlo = sb + PLANE_B;
        const uint32_t pBhi = sb + 2 * PLANE_B;
        const uint32_t pBlo = sb + 3 * PLANE_B;

#pragma unroll
        for (int ks = 0; ks < 2; ks++) {
            const uint32_t akk = ks ? ak1 : ak0;
            const uint32_t bkk = ks ? bk1 : bk0;
            uint32_t bhi[4][2], blo[4][2];
#pragma unroll
            for (int q = 0; q < 2; q++) {
                uint32_t ad = pBhi + b_row + q * 16 * 64 + bkk;
                LDM4(bhi[2 * q][0], bhi[2 * q][1], bhi[2 * q + 1][0],
                     bhi[2 * q + 1][1], ad);
                ad = pBlo + b_row + q * 16 * 64 + bkk;
                LDM4(blo[2 * q][0], blo[2 * q][1], blo[2 * q + 1][0],
                     blo[2 * q + 1][1], ad);
            }
#pragma unroll
            for (int mt = 0; mt < 4; mt++) {
                uint32_t ahi[4], alo[4];
                uint32_t ad = pAhi + a_row + mt * 16 * 64 + akk;
                LDM4(ahi[0], ahi[1], ahi[2], ahi[3], ad);
                ad = pAlo + a_row + mt * 16 * 64 + akk;
                LDM4(alo[0], alo[1], alo[2], alo[3], ad);
#pragma unroll
                for (int nt = 0; nt < 4; nt++) {
                    MMA_BF16(acc[mt][nt], ahi, bhi[nt]);
                    MMA_BF16(acc[mt][nt], ahi, blo[nt]);
                    MMA_BF16(acc[mt][nt], alo, bhi[nt]);
                }
            }
        }
    }

    const int gid = lane >> 2;
    const int tig = lane & 3;
#pragma unroll
    for (int mt = 0; mt < 4; mt++) {
        int row0 = bm + warp_m * 64 + mt * 16 + gid;
        int row1 = row0 + 8;
#pragma unroll
        for (int nt = 0; nt < 4; nt++) {
            int col = bn + warp_n * 32 + nt * 8 + tig * 2;
            if (row0 < M)
                *(float2*)&C[(size_t)row0 * N + col] =
                    make_float2(acc[mt][nt][0], acc[mt][nt][1]);
            if (row1 < M)
                *(float2*)&C[(size_t)row1 * N + col] =
                    make_float2(acc[mt][nt][2], acc[mt][nt][3]);
        }
    }
}

// ---------------- elementwise gate kernels (float4 vectorized) ---------------
static __device__ __forceinline__ float sigmoidf_(float x) {
    return 1.f / (1.f + expf(-x));
}
static __device__ __forceinline__ void split_store(bf16* hhi, bf16* hlo,
                                                   int i4, float4 h) {
    bf16 h0 = __float2bfloat16(h.x), h1 = __float2bfloat16(h.y);
    bf16 h2 = __float2bfloat16(h.z), h3 = __float2bfloat16(h.w);
    ((__nv_bfloat162*)hhi)[i4 * 2]     = __nv_bfloat162(h0, h1);
    ((__nv_bfloat162*)hhi)[i4 * 2 + 1] = __nv_bfloat162(h2, h3);
    ((__nv_bfloat162*)hlo)[i4 * 2] = __nv_bfloat162(
        __float2bfloat16(h.x - __bfloat162float(h0)),
        __float2bfloat16(h.y - __bfloat162float(h1)));
    ((__nv_bfloat162*)hlo)[i4 * 2 + 1] = __nv_bfloat162(
        __float2bfloat16(h.z - __bfloat162float(h2)),
        __float2bfloat16(h.w - __bfloat162float(h3)));
}

__global__ void leaf_eltwise(const float* __restrict__ g,
                             const float* __restrict__ b,
                             float* __restrict__ c,
                             bf16* __restrict__ hhi, bf16* __restrict__ hlo,
                             int rows) {
    int i4 = blockIdx.x * blockDim.x + threadIdx.x;
    if (i4 >= rows * (MEMD / 4)) return;
    int row = i4 / (MEMD / 4);
    int m = (i4 - row * (MEMD / 4)) * 4;
    const float* gr = g + (size_t)row * 3 * MEMD;
    float4 gi = *(const float4*)&gr[m];
    float4 go = *(const float4*)&gr[MEMD + m];
    float4 gu = *(const float4*)&gr[2 * MEMD + m];
    float4 bi = *(const float4*)&b[MEMD + m];
    float4 bo = *(const float4*)&b[2 * MEMD + m];
    float4 bu = *(const float4*)&b[3 * MEMD + m];
    float4 cc, hh;
#define LEAF1(X)                                                              \
    {                                                                         \
        float iv = sigmoidf_(gi.X + bi.X), ov = sigmoidf_(go.X + bo.X);       \
        float uv = tanhf(gu.X + bu.X);                                        \
        cc.X = iv * uv; hh.X = ov * tanhf(cc.X);                              \
    }
    LEAF1(x) LEAF1(y) LEAF1(z) LEAF1(w)
#undef LEAF1
    ((float4*)c)[i4] = cc;
    split_store(hhi, hlo, i4, hh);
}

__global__ void node_eltwise(const float* __restrict__ g,
                             const float* __restrict__ b,
                             const float* __restrict__ c_prev,
                             float* __restrict__ c,
                             bf16* __restrict__ hhi, bf16* __restrict__ hlo,
                             float* __restrict__ hroot, int rows, int nsl) {
    int i4 = blockIdx.x * blockDim.x + threadIdx.x;
    if (i4 >= rows * (MEMD / 4)) return;
    int row = i4 / (MEMD / 4);
    int m = (i4 - row * (MEMD / 4)) * 4;
    const size_t sstride = (size_t)rows * 5 * MEMD;
    const float* gr = g + (size_t)row * 5 * MEMD;
    float4 gi = *(const float4*)&gr[m];
    float4 go = *(const float4*)&gr[MEMD + m];
    float4 gu = *(const float4*)&gr[2 * MEMD + m];
    float4 gfl = *(const float4*)&gr[3 * MEMD + m];
    float4 gfr = *(const float4*)&gr[4 * MEMD + m];
    for (int s = 1; s < nsl; s++) {
        const float* gs = gr + s * sstride;
        float4 t;
        t = *(const float4*)&gs[m];
        gi.x += t.x; gi.y += t.y; gi.z += t.z; gi.w += t.w;
        t = *(const float4*)&gs[MEMD + m];
        go.x += t.x; go.y += t.y; go.z += t.z; go.w += t.w;
        t = *(const float4*)&gs[2 * MEMD + m];
        gu.x += t.x; gu.y += t.y; gu.z += t.z; gu.w += t.w;
        t = *(const float4*)&gs[3 * MEMD + m];
        gfl.x += t.x; gfl.y += t.y; gfl.z += t.z; gfl.w += t.w;
        t = *(const float4*)&gs[4 * MEMD + m];
        gfr.x += t.x; gfr.y += t.y; gfr.z += t.z; gfr.w += t.w;
    }
    const float* cpr = c_prev + (size_t)row * 2 * MEMD;
    float4 bi = *(const float4*)&b[MEMD + m];
    float4 bo = *(const float4*)&b[2 * MEMD + m];
    float4 bu = *(const float4*)&b[3 * MEMD + m];
    float4 bf = *(const float4*)&b[m];
    float4 cl = *(const float4*)&cpr[m];
    float4 cr = *(const float4*)&cpr[MEMD + m];
    float4 cc, hh;
#define NODE1(X)                                                              \
    {                                                                         \
        float iv = sigmoidf_(gi.X + bi.X), ov = sigmoidf_(go.X + bo.X);       \
        float uv = tanhf(gu.X + bu.X);                                        \
        float fl = sigmoidf_(gfl.X + bf.X), fr = sigmoidf_(gfr.X + bf.X);     \
        cc.X = fmaf(iv, uv, fmaf(fl, cl.X, fr * cr.X));                       \
        hh.X = ov * tanhf(cc.X);                                              \
    }
    NODE1(x) NODE1(y) NODE1(z) NODE1(w)
#undef NODE1
    ((float4*)c)[i4] = cc;
    if (hroot)
        ((float4*)hroot)[i4] = hh;
    else
        split_store(hhi, hlo, i4, hh);
}

// ---------------- launch -----------------------------------------------------
extern "C" void kernel_launch(void* const* d_in, const int* in_sizes, int n_in,
                              void* d_out, int out_size) {
    const float* inputs  = (const float*)d_in[0];
    const float* w_fioux = (const float*)d_in[1];
    const float* b       = (const float*)d_in[2];
    const float* w_iouh  = (const float*)d_in[3];
    const float* w_fh    = (const float*)d_in[4];
    float* out = (float*)d_out;

    float *scr, *c0, *c1;
    bf16 *h0hi, *h0lo, *h1hi, *h1lo, *xhi, *xlo, *wxhi, *wxlo, *wchi, *wclo;
    cudaGetSymbolAddress((void**)&scr, g_scr);
    cudaGetSymbolAddress((void**)&c0, g_c0);
    cudaGetSymbolAddress((void**)&c1, g_c1);
    cudaGetSymbolAddress((void**)&h0hi, g_h0hi);
    cudaGetSymbolAddress((void**)&h0lo, g_h0lo);
    cudaGetSymbolAddress((void**)&h1hi, g_h1hi);
    cudaGetSymbolAddress((void**)&h1lo, g_h1lo);
    cudaGetSymbolAddress((void**)&xhi, g_xhi);
    cudaGetSymbolAddress((void**)&xlo, g_xlo);
    cudaGetSymbolAddress((void**)&wxhi, g_wxhi);
    cudaGetSymbolAddress((void**)&wxlo, g_wxlo);
    cudaGetSymbolAddress((void**)&wchi, g_wchi);
    cudaGetSymbolAddress((void**)&wclo, g_wclo);

    cudaFuncSetAttribute(gemm_split, cudaFuncAttributeMaxDynamicSharedMemorySize,
                         SMEM_DYN);

    const int rowsL = BB * NL;  // 16384

    {
        int n0 = rowsL * INDIM / 4;
        int n1 = 3 * MEMD * INDIM / 4;
        int n2 = 3 * MEMD * 2 * MEMD / 4;
        int n3 = 2 * MEMD * 2 * MEMD / 4;
        size_t off = (size_t)3 * MEMD * 2 * MEMD;
        int tot = n0 + n1 + n2 + n3;
        split_all<<<(tot + 255) / 256, 256>>>(
            inputs, xhi, xlo, n0,
            w_fioux + (size_t)MEMD * INDIM, wxhi, wxlo, n1,
            w_iouh, wchi, wclo, n2,
            w_fh, wchi + off, wclo + off, n3);
    }

    gemm_split<<<dim3(3 * MEMD / BN, rowsL / BM, 1), 256, SMEM_DYN>>>(
        xhi, xlo, wxhi, wxlo, scr, rowsL, 3 * MEMD, INDIM, INDIM / BK);
    leaf_eltwise<<<(rowsL * MEMD / 4 + 255) / 256, 256>>>(scr, b, c0, h0hi,
                                                          h0lo, rowsL);

    float *cp = c0, *cn = c1;
    bf16 *hpi = h0hi, *hpl = h0lo, *hni = h1hi, *hnl = h1lo;
    for (int n = NL / 2; n >= 1; n >>= 1) {
        int rows = BB * n;
        int ks = rows >= 1024 ? 1
               : rows == 512 ? 2
               : rows == 256 ? 4
               : rows == 128 ? 8 : 16;
        int kcps = (2 * MEMD / BK) / ks;   // 64 / ks
        int gy = (rows + BM - 1) / BM;
        gemm_split<<<dim3(5 * MEMD / BN, gy, ks), 256, SMEM_DYN>>>(
            hpi, hpl, wchi, wclo, scr, rows, 5 * MEMD, 2 * MEMD, kcps);
        node_eltwise<<<(rows * MEMD / 4 + 255) / 256, 256>>>(
            scr, b, cp, cn, hni, hnl, (n == 1) ? out : (float*)nullptr, rows, ks);
        float* tc = cp; cp = cn; cn = tc;
        bf16* t;
        t = hpi; hpi = hni; hni = t;
        t = hpl; hpl = hnl; hnl = t;
    }
}

// round 8
// speedup vs baseline: 4.2381x; 1.0126x over previous
#include <cuda_runtime.h>
#include <cuda_bf16.h>
#include <math.h>
#include <stdint.h>

#define BB 32
#define NL 512
#define INDIM 1024
#define MEMD 1024

typedef __nv_bfloat16 bf16;

// ---------------- static scratch (no runtime allocation allowed) -------------
__device__ __align__(256) float g_c0[BB * NL * MEMD];
__device__ __align__(256) float g_c1[(BB * NL / 2) * MEMD];
__device__ __align__(256) bf16 g_h0hi[BB * NL * MEMD];
__device__ __align__(256) bf16 g_h0lo[BB * NL * MEMD];
__device__ __align__(256) bf16 g_h1hi[(BB * NL / 2) * MEMD];
__device__ __align__(256) bf16 g_h1lo[(BB * NL / 2) * MEMD];
__device__ __align__(256) bf16 g_xhi[(size_t)BB * NL * INDIM];
__device__ __align__(256) bf16 g_xlo[(size_t)BB * NL * INDIM];
__device__ __align__(256) bf16 g_wxhi[(size_t)3 * MEMD * INDIM];
__device__ __align__(256) bf16 g_wxlo[(size_t)3 * MEMD * INDIM];
__device__ __align__(256) bf16 g_wchi[(size_t)5 * MEMD * 2 * MEMD];
__device__ __align__(256) bf16 g_wclo[(size_t)5 * MEMD * 2 * MEMD];
__device__ __align__(256) float g_scr[(size_t)BB * NL * 3 * MEMD];

// ---------------- fused fp32 -> bf16 hi/lo split (4 segments, 1 launch) ------
__global__ void split_all(const float* __restrict__ s0, bf16* h0, bf16* l0, int n0,
                          const float* __restrict__ s1, bf16* h1, bf16* l1, int n1,
                          const float* __restrict__ s2, bf16* h2, bf16* l2, int n2,
                          const float* __restrict__ s3, bf16* h3, bf16* l3, int n3) {
    int i = blockIdx.x * blockDim.x + threadIdx.x;
    const float* s;
    bf16 *hi, *lo;
    int j = i;
    if (j < n0) { s = s0; hi = h0; lo = l0; }
    else {
        j -= n0;
        if (j < n1) { s = s1; hi = h1; lo = l1; }
        else {
            j -= n1;
            if (j < n2) { s = s2; hi = h2; lo = l2; }
            else {
                j -= n2;
                if (j >= n3) return;
                s = s3; hi = h3; lo = l3;
            }
        }
    }
    float4 v = ((const float4*)s)[j];
    bf16 a0 = __float2bfloat16(v.x), a1 = __float2bfloat16(v.y);
    bf16 a2 = __float2bfloat16(v.z), a3 = __float2bfloat16(v.w);
    ((__nv_bfloat162*)hi)[j * 2]     = __nv_bfloat162(a0, a1);
    ((__nv_bfloat162*)hi)[j * 2 + 1] = __nv_bfloat162(a2, a3);
    ((__nv_bfloat162*)lo)[j * 2] = __nv_bfloat162(
        __float2bfloat16(v.x - __bfloat162float(a0)),
        __float2bfloat16(v.y - __bfloat162float(a1)));
    ((__nv_bfloat162*)lo)[j * 2 + 1] = __nv_bfloat162(
        __float2bfloat16(v.z - __bfloat162float(a2)),
        __float2bfloat16(v.w - __bfloat162float(a3)));
}

// ============================================================================
// split-bf16 GEMM: C[M,N] = (Ahi+Alo)[M,K] * (Whi+Wlo)[N,K]^T  (K-major)
// BM=BN=128, BK=32. 8 warps (2x4): warp tile 64x32 = 4x4 m16n8k16 x 3 splits.
// XOR-swizzled 64B smem rows; 3-stage cp.async; one __syncthreads per chunk.
// Split-type-major MMA order (chain dist 4) + A-fragment double buffering.
// gridDim.z = deterministic K-slices writing disjoint partial outputs.
// ============================================================================
#define BM 128
#define BN 128
#define BK 32
#define PLANE_B 8192                 // 128 rows * 64B
#define STAGE_B (4 * PLANE_B)        // Ahi,Alo,Whi,Wlo
#define NSTG 3
#define SMEM_DYN (NSTG * STAGE_B + 128)

static __device__ __forceinline__ uint32_t smem_u32(const void* p) {
    uint32_t a;
    asm("{ .reg .u64 t; cvta.to.shared.u64 t, %1; cvt.u32.u64 %0, t; }"
        : "=r"(a) : "l"(p));
    return a;
}

#define LDM4(r0, r1, r2, r3, addr)                                            \
    asm volatile("ldmatrix.sync.aligned.m8n8.x4.shared.b16 {%0,%1,%2,%3}, [%4];" \
                 : "=r"(r0), "=r"(r1), "=r"(r2), "=r"(r3) : "r"(addr))

#define MMA_BF16(d, a, b)                                                     \
    asm volatile("mma.sync.aligned.m16n8k16.row.col.f32.bf16.bf16.f32 "       \
                 "{%0,%1,%2,%3},{%4,%5,%6,%7},{%8,%9},{%0,%1,%2,%3};"         \
                 : "+f"(d[0]), "+f"(d[1]), "+f"(d[2]), "+f"(d[3])             \
                 : "r"(a[0]), "r"(a[1]), "r"(a[2]), "r"(a[3]),                \
                   "r"(b[0]), "r"(b[1]))

static __device__ __forceinline__ void load_stage(
    const bf16* __restrict__ Ahi, const bf16* __restrict__ Alo,
    const bf16* __restrict__ Whi, const bf16* __restrict__ Wlo,
    int M, int K, int bm, int bn, int k0, uint32_t sbase, int tid) {
#pragma unroll
    for (int i = 0; i < 8; i++) {
        int l = tid + 256 * i;          // 0..2047
        int plane = l >> 9;             // 0:Ahi 1:Alo 2:Whi 3:Wlo
        int c = l & 511;
        int row = c >> 2;
        int ch = c & 3;
        int sc = ch ^ ((row >> 1) & 3);          // swizzled 16B chunk
        uint32_t dst = sbase + plane * PLANE_B + row * 64 + sc * 16;
        if (plane < 2) {
            const bf16* base = plane ? Alo : Ahi;
            int gr = bm + row;
            int ok = gr < M;
            const bf16* g = base + (size_t)(ok ? gr : 0) * K + k0 + ch * 8;
            int sz = ok ? 16 : 0;
            asm volatile("cp.async.cg.shared.global [%0], [%1], 16, %2;\n"
                         :: "r"(dst), "l"(g), "r"(sz));
        } else {
            const bf16* base = (plane == 2) ? Whi : Wlo;
            const bf16* g = base + (size_t)(bn + row) * K + k0 + ch * 8;
            asm volatile("cp.async.cg.shared.global [%0], [%1], 16;\n"
                         :: "r"(dst), "l"(g));
        }
    }
}

__global__ __launch_bounds__(256, 2)
void gemm_split(const bf16* __restrict__ Ahi, const bf16* __restrict__ Alo,
                const bf16* __restrict__ Whi, const bf16* __restrict__ Wlo,
                float* __restrict__ C, int M, int N, int K, int kcps) {
    extern __shared__ __align__(128) char smem_raw[];
    uint32_t sbase = smem_u32(smem_raw);
    sbase = (sbase + 127u) & ~127u;

    const int tid = threadIdx.x;
    const int wid = tid >> 5;
    const int lane = tid & 31;
    const int warp_m = wid >> 2;
    const int warp_n = wid & 3;
    const int bm = blockIdx.y * BM;
    const int bn = blockIdx.x * BN;
    const int kbase = blockIdx.z * kcps * BK;
    C += (size_t)blockIdx.z * M * N;    // partial slice

    // per-lane ldmatrix addressing (byte offsets within a plane)
    const int ra = ((lane >> 3) & 1) * 8 + (lane & 7);
    const int cha = (lane >> 4) & 1;
    const int swza = (ra >> 1) & 3;
    const uint32_t a_row = (uint32_t)(warp_m * 64 + ra) * 64;
    const uint32_t ak0 = ((cha ^ swza) << 4);
    const uint32_t ak1 = (((2 + cha) ^ swza) << 4);

    const int rb = ((lane >> 4) & 1) * 8 + (lane & 7);
    const int chb = (lane >> 3) & 1;
    const int swzb = (rb >> 1) & 3;
    const uint32_t b_row = (uint32_t)(warp_n * 32 + rb) * 64;
    const uint32_t bk0 = ((chb ^ swzb) << 4);
    const uint32_t bk1 = (((2 + chb) ^ swzb) << 4);

    float acc[4][4][4];
#pragma unroll
    for (int mt = 0; mt < 4; mt++)
#pragma unroll
        for (int nt = 0; nt < 4; nt++)
#pragma unroll
            for (int e = 0; e < 4; e++) acc[mt][nt][e] = 0.f;

    load_stage(Ahi, Alo, Whi, Wlo, M, K, bm, bn, kbase, sbase, tid);
    asm volatile("cp.async.commit_group;\n");
    if (1 < kcps)
        load_stage(Ahi, Alo, Whi, Wlo, M, K, bm, bn, kbase + BK,
                   sbase + STAGE_B, tid);
    asm volatile("cp.async.commit_group;\n");

    for (int it = 0; it < kcps; it++) {
        asm volatile("cp.async.wait_group 1;\n");
        __syncthreads();

        if (it + 2 < kcps)
            load_stage(Ahi, Alo, Whi, Wlo, M, K, bm, bn, kbase + (it + 2) * BK,
                       sbase + ((it + 2) % NSTG) * STAGE_B, tid);
        asm volatile("cp.async.commit_group;\n");

        const uint32_t sb = sbase + (it % NSTG) * STAGE_B;
        const uint32_t pAhi = sb;
        const uint32_t pAlo = sb + PLANE_B;
        const uint32_t pBhi = sb + 2 * PLANE_B;
        const uint32_t pBlo = sb + 3 * PLANE_B;

#pragma unroll
        for (int ks = 0; ks < 2; ks++) {
            const uint32_t akk = ks ? ak1 : ak0;
            const uint32_t bkk = ks ? bk1 : bk0;
            uint32_t bhi[4][2], blo[4][2];
#pragma unroll
            for (int q = 0; q < 2; q++) {
                uint32_t ad = pBhi + b_row + q * 16 * 64 + bkk;
                LDM4(bhi[2 * q][0], bhi[2 * q][1], bhi[2 * q + 1][0],
                     bhi[2 * q + 1][1], ad);
                ad = pBlo + b_row + q * 16 * 64 + bkk;
                LDM4(blo[2 * q][0], blo[2 * q][1], blo[2 * q + 1][0],
                     blo[2 * q + 1][1], ad);
            }
            // A fragment double buffer across mt
            uint32_t ahi[2][4], alo[2][4];
            {
                uint32_t ad = pAhi + a_row + akk;
                LDM4(ahi[0][0], ahi[0][1], ahi[0][2], ahi[0][3], ad);
                ad = pAlo + a_row + akk;
                LDM4(alo[0][0], alo[0][1], alo[0][2], alo[0][3], ad);
            }
#pragma unroll
            for (int mt = 0; mt < 4; mt++) {
                const int cur = mt & 1;
                if (mt < 3) {
                    uint32_t ad = pAhi + a_row + (mt + 1) * 16 * 64 + akk;
                    LDM4(ahi[cur ^ 1][0], ahi[cur ^ 1][1], ahi[cur ^ 1][2],
                         ahi[cur ^ 1][3], ad);
                    ad = pAlo + a_row + (mt + 1) * 16 * 64 + akk;
                    LDM4(alo[cur ^ 1][0], alo[cur ^ 1][1], alo[cur ^ 1][2],
                         alo[cur ^ 1][3], ad);
                }
                // split-type-major: chain distance 4 per accumulator
#pragma unroll
                for (int nt = 0; nt < 4; nt++)
                    MMA_BF16(acc[mt][nt], ahi[cur], bhi[nt]);
#pragma unroll
                for (int nt = 0; nt < 4; nt++)
                    MMA_BF16(acc[mt][nt], ahi[cur], blo[nt]);
#pragma unroll
                for (int nt = 0; nt < 4; nt++)
                    MMA_BF16(acc[mt][nt], alo[cur], bhi[nt]);
            }
        }
    }

    const int gid = lane >> 2;
    const int tig = lane & 3;
#pragma unroll
    for (int mt = 0; mt < 4; mt++) {
        int row0 = bm + warp_m * 64 + mt * 16 + gid;
        int row1 = row0 + 8;
#pragma unroll
        for (int nt = 0; nt < 4; nt++) {
            int col = bn + warp_n * 32 + nt * 8 + tig * 2;
            if (row0 < M)
                *(float2*)&C[(size_t)row0 * N + col] =
                    make_float2(acc[mt][nt][0], acc[mt][nt][1]);
            if (row1 < M)
                *(float2*)&C[(size_t)row1 * N + col] =
                    make_float2(acc[mt][nt][2], acc[mt][nt][3]);
        }
    }
}

// ---------------- elementwise gate kernels (float4 vectorized) ---------------
static __device__ __forceinline__ float sigmoidf_(float x) {
    return 1.f / (1.f + expf(-x));
}
static __device__ __forceinline__ void split_store(bf16* hhi, bf16* hlo,
                                                   int i4, float4 h) {
    bf16 h0 = __float2bfloat16(h.x), h1 = __float2bfloat16(h.y);
    bf16 h2 = __float2bfloat16(h.z), h3 = __float2bfloat16(h.w);
    ((__nv_bfloat162*)hhi)[i4 * 2]     = __nv_bfloat162(h0, h1);
    ((__nv_bfloat162*)hhi)[i4 * 2 + 1] = __nv_bfloat162(h2, h3);
    ((__nv_bfloat162*)hlo)[i4 * 2] = __nv_bfloat162(
        __float2bfloat16(h.x - __bfloat162float(h0)),
        __float2bfloat16(h.y - __bfloat162float(h1)));
    ((__nv_bfloat162*)hlo)[i4 * 2 + 1] = __nv_bfloat162(
        __float2bfloat16(h.z - __bfloat162float(h2)),
        __float2bfloat16(h.w - __bfloat162float(h3)));
}

__global__ void leaf_eltwise(const float* __restrict__ g,
                             const float* __restrict__ b,
                             float* __restrict__ c,
                             bf16* __restrict__ hhi, bf16* __restrict__ hlo,
                             int rows) {
    int i4 = blockIdx.x * blockDim.x + threadIdx.x;
    if (i4 >= rows * (MEMD / 4)) return;
    int row = i4 / (MEMD / 4);
    int m = (i4 - row * (MEMD / 4)) * 4;
    const float* gr = g + (size_t)row * 3 * MEMD;
    float4 gi = *(const float4*)&gr[m];
    float4 go = *(const float4*)&gr[MEMD + m];
    float4 gu = *(const float4*)&gr[2 * MEMD + m];
    float4 bi = *(const float4*)&b[MEMD + m];
    float4 bo = *(const float4*)&b[2 * MEMD + m];
    float4 bu = *(const float4*)&b[3 * MEMD + m];
    float4 cc, hh;
#define LEAF1(X)                                                              \
    {                                                                         \
        float iv = sigmoidf_(gi.X + bi.X), ov = sigmoidf_(go.X + bo.X);       \
        float uv = tanhf(gu.X + bu.X);                                        \
        cc.X = iv * uv; hh.X = ov * tanhf(cc.X);                              \
    }
    LEAF1(x) LEAF1(y) LEAF1(z) LEAF1(w)
#undef LEAF1
    ((float4*)c)[i4] = cc;
    split_store(hhi, hlo, i4, hh);
}

__global__ void node_eltwise(const float* __restrict__ g,
                             const float* __restrict__ b,
                             const float* __restrict__ c_prev,
                             float* __restrict__ c,
                             bf16* __restrict__ hhi, bf16* __restrict__ hlo,
                             float* __restrict__ hroot, int rows, int nsl) {
    int i4 = blockIdx.x * blockDim.x + threadIdx.x;
    if (i4 >= rows * (MEMD / 4)) return;
    int row = i4 / (MEMD / 4);
    int m = (i4 - row * (MEMD / 4)) * 4;
    const size_t sstride = (size_t)rows * 5 * MEMD;
    const float* gr = g + (size_t)row * 5 * MEMD;
    float4 gi = *(const float4*)&gr[m];
    float4 go = *(const float4*)&gr[MEMD + m];
    float4 gu = *(const float4*)&gr[2 * MEMD + m];
    float4 gfl = *(const float4*)&gr[3 * MEMD + m];
    float4 gfr = *(const float4*)&gr[4 * MEMD + m];
    for (int s = 1; s < nsl; s++) {
        const float* gs = gr + s * sstride;
        float4 t;
        t = *(const float4*)&gs[m];
        gi.x += t.x; gi.y += t.y; gi.z += t.z; gi.w += t.w;
        t = *(const float4*)&gs[MEMD + m];
        go.x += t.x; go.y += t.y; go.z += t.z; go.w += t.w;
        t = *(const float4*)&gs[2 * MEMD + m];
        gu.x += t.x; gu.y += t.y; gu.z += t.z; gu.w += t.w;
        t = *(const float4*)&gs[3 * MEMD + m];
        gfl.x += t.x; gfl.y += t.y; gfl.z += t.z; gfl.w += t.w;
        t = *(const float4*)&gs[4 * MEMD + m];
        gfr.x += t.x; gfr.y += t.y; gfr.z += t.z; gfr.w += t.w;
    }
    const float* cpr = c_prev + (size_t)row * 2 * MEMD;
    float4 bi = *(const float4*)&b[MEMD + m];
    float4 bo = *(const float4*)&b[2 * MEMD + m];
    float4 bu = *(const float4*)&b[3 * MEMD + m];
    float4 bf = *(const float4*)&b[m];
    float4 cl = *(const float4*)&cpr[m];
    float4 cr = *(const float4*)&cpr[MEMD + m];
    float4 cc, hh;
#define NODE1(X)                                                              \
    {                                                                         \
        float iv = sigmoidf_(gi.X + bi.X), ov = sigmoidf_(go.X + bo.X);       \
        float uv = tanhf(gu.X + bu.X);                                        \
        float fl = sigmoidf_(gfl.X + bf.X), fr = sigmoidf_(gfr.X + bf.X);     \
        cc.X = fmaf(iv, uv, fmaf(fl, cl.X, fr * cr.X));                       \
        hh.X = ov * tanhf(cc.X);                                              \
    }
    NODE1(x) NODE1(y) NODE1(z) NODE1(w)
#undef NODE1
    ((float4*)c)[i4] = cc;
    if (hroot)
        ((float4*)hroot)[i4] = hh;
    else
        split_store(hhi, hlo, i4, hh);
}

// ---------------- launch -----------------------------------------------------
extern "C" void kernel_launch(void* const* d_in, const int* in_sizes, int n_in,
                              void* d_out, int out_size) {
    const float* inputs  = (const float*)d_in[0];
    const float* w_fioux = (const float*)d_in[1];
    const float* b       = (const float*)d_in[2];
    const float* w_iouh  = (const float*)d_in[3];
    const float* w_fh    = (const float*)d_in[4];
    float* out = (float*)d_out;

    float *scr, *c0, *c1;
    bf16 *h0hi, *h0lo, *h1hi, *h1lo, *xhi, *xlo, *wxhi, *wxlo, *wchi, *wclo;
    cudaGetSymbolAddress((void**)&scr, g_scr);
    cudaGetSymbolAddress((void**)&c0, g_c0);
    cudaGetSymbolAddress((void**)&c1, g_c1);
    cudaGetSymbolAddress((void**)&h0hi, g_h0hi);
    cudaGetSymbolAddress((void**)&h0lo, g_h0lo);
    cudaGetSymbolAddress((void**)&h1hi, g_h1hi);
    cudaGetSymbolAddress((void**)&h1lo, g_h1lo);
    cudaGetSymbolAddress((void**)&xhi, g_xhi);
    cudaGetSymbolAddress((void**)&xlo, g_xlo);
    cudaGetSymbolAddress((void**)&wxhi, g_wxhi);
    cudaGetSymbolAddress((void**)&wxlo, g_wxlo);
    cudaGetSymbolAddress((void**)&wchi, g_wchi);
    cudaGetSymbolAddress((void**)&wclo, g_wclo);

    cudaFuncSetAttribute(gemm_split, cudaFuncAttributeMaxDynamicSharedMemorySize,
                         SMEM_DYN);

    const int rowsL = BB * NL;  // 16384

    {
        int n0 = rowsL * INDIM / 4;
        int n1 = 3 * MEMD * INDIM / 4;
        int n2 = 3 * MEMD * 2 * MEMD / 4;
        int n3 = 2 * MEMD * 2 * MEMD / 4;
        size_t off = (size_t)3 * MEMD * 2 * MEMD;
        int tot = n0 + n1 + n2 + n3;
        split_all<<<(tot + 255) / 256, 256>>>(
            inputs, xhi, xlo, n0,
            w_fioux + (size_t)MEMD * INDIM, wxhi, wxlo, n1,
            w_iouh, wchi, wclo, n2,
            w_fh, wchi + off, wclo + off, n3);
    }

    gemm_split<<<dim3(3 * MEMD / BN, rowsL / BM, 1), 256, SMEM_DYN>>>(
        xhi, xlo, wxhi, wxlo, scr, rowsL, 3 * MEMD, INDIM, INDIM / BK);
    leaf_eltwise<<<(rowsL * MEMD / 4 + 255) / 256, 256>>>(scr, b, c0, h0hi,
                                                          h0lo, rowsL);

    float *cp = c0, *cn = c1;
    bf16 *hpi = h0hi, *hpl = h0lo, *hni = h1hi, *hnl = h1lo;
    for (int n = NL / 2; n >= 1; n >>= 1) {
        int rows = BB * n;
        int ks = rows >= 1024 ? 1
               : rows == 512 ? 2
               : rows == 256 ? 4
               : rows == 128 ? 8 : 16;
        int kcps = (2 * MEMD / BK) / ks;   // 64 / ks
        int gy = (rows + BM - 1) / BM;
        gemm_split<<<dim3(5 * MEMD / BN, gy, ks), 256, SMEM_DYN>>>(
            hpi, hpl, wchi, wclo, scr, rows, 5 * MEMD, 2 * MEMD, kcps);
        node_eltwise<<<(rows * MEMD / 4 + 255) / 256, 256>>>(
            scr, b, cp, cn, hni, hnl, (n == 1) ? out : (float*)nullptr, rows, ks);
        float* tc = cp; cp = cn; cn = tc;
        bf16* t;
        t = hpi; hpi = hni; hni = t;
        t = hpl; hpl = hnl; hnl = t;
    }
}

// round 9
// speedup vs baseline: 4.5479x; 1.0731x over previous
#include <cuda_runtime.h>
#include <cuda_bf16.h>
#include <math.h>
#include <stdint.h>

#define BB 32
#define NL 512
#define INDIM 1024
#define MEMD 1024

typedef __nv_bfloat16 bf16;

// ---------------- static scratch (no runtime allocation allowed) -------------
__device__ __align__(256) float g_c0[BB * NL * MEMD];
__device__ __align__(256) float g_c1[(BB * NL / 2) * MEMD];
__device__ __align__(256) bf16 g_h0hi[BB * NL * MEMD];
__device__ __align__(256) bf16 g_h0lo[BB * NL * MEMD];
__device__ __align__(256) bf16 g_h1hi[(BB * NL / 2) * MEMD];
__device__ __align__(256) bf16 g_h1lo[(BB * NL / 2) * MEMD];
__device__ __align__(256) bf16 g_xhi[(size_t)BB * NL * INDIM];
__device__ __align__(256) bf16 g_xlo[(size_t)BB * NL * INDIM];
__device__ __align__(256) bf16 g_wxhi[(size_t)3 * MEMD * INDIM];
__device__ __align__(256) bf16 g_wxlo[(size_t)3 * MEMD * INDIM];
__device__ __align__(256) bf16 g_wchi[(size_t)5 * MEMD * 2 * MEMD];
__device__ __align__(256) bf16 g_wclo[(size_t)5 * MEMD * 2 * MEMD];
__device__ __align__(256) float g_scr[(size_t)BB * NL * 3 * MEMD];

// ---------------- fused fp32 -> bf16 hi/lo split (4 segments, 1 launch) ------
__global__ void split_all(const float* __restrict__ s0, bf16* h0, bf16* l0, int n0,
                          const float* __restrict__ s1, bf16* h1, bf16* l1, int n1,
                          const float* __restrict__ s2, bf16* h2, bf16* l2, int n2,
                          const float* __restrict__ s3, bf16* h3, bf16* l3, int n3) {
    int i = blockIdx.x * blockDim.x + threadIdx.x;
    const float* s;
    bf16 *hi, *lo;
    int j = i;
    if (j < n0) { s = s0; hi = h0; lo = l0; }
    else {
        j -= n0;
        if (j < n1) { s = s1; hi = h1; lo = l1; }
        else {
            j -= n1;
            if (j < n2) { s = s2; hi = h2; lo = l2; }
            else {
                j -= n2;
                if (j >= n3) return;
                s = s3; hi = h3; lo = l3;
            }
        }
    }
    float4 v = ((const float4*)s)[j];
    bf16 a0 = __float2bfloat16(v.x), a1 = __float2bfloat16(v.y);
    bf16 a2 = __float2bfloat16(v.z), a3 = __float2bfloat16(v.w);
    ((__nv_bfloat162*)hi)[j * 2]     = __nv_bfloat162(a0, a1);
    ((__nv_bfloat162*)hi)[j * 2 + 1] = __nv_bfloat162(a2, a3);
    ((__nv_bfloat162*)lo)[j * 2] = __nv_bfloat162(
        __float2bfloat16(v.x - __bfloat162float(a0)),
        __float2bfloat16(v.y - __bfloat162float(a1)));
    ((__nv_bfloat162*)lo)[j * 2 + 1] = __nv_bfloat162(
        __float2bfloat16(v.z - __bfloat162float(a2)),
        __float2bfloat16(v.w - __bfloat162float(a3)));
}

// ============================================================================
// split-bf16 GEMM: C[M,N] = (Ahi+Alo)[M,K] * (Whi+Wlo)[N,K]^T  (K-major)
// BM=BN=128, BK=32. 8 warps (2x4): warp tile 64x32 = 4x4 m16n8k16 x 3 splits.
// XOR-swizzled 64B smem rows; 3-stage cp.async; one __syncthreads per chunk.
// mt-pair interleaved MMA order (chain dist 8); prefetch issued mid-compute.
// gridDim.z = deterministic K-slices writing disjoint partial outputs.
// ============================================================================
#define BM 128
#define BN 128
#define BK 32
#define PLANE_B 8192                 // 128 rows * 64B
#define STAGE_B (4 * PLANE_B)        // Ahi,Alo,Whi,Wlo
#define NSTG 3
#define SMEM_DYN (NSTG * STAGE_B + 128)

static __device__ __forceinline__ uint32_t smem_u32(const void* p) {
    uint32_t a;
    asm("{ .reg .u64 t; cvta.to.shared.u64 t, %1; cvt.u32.u64 %0, t; }"
        : "=r"(a) : "l"(p));
    return a;
}

#define LDM4(r0, r1, r2, r3, addr)                                            \
    asm volatile("ldmatrix.sync.aligned.m8n8.x4.shared.b16 {%0,%1,%2,%3}, [%4];" \
                 : "=r"(r0), "=r"(r1), "=r"(r2), "=r"(r3) : "r"(addr))

#define MMA_BF16(d, a, b)                                                     \
    asm volatile("mma.sync.aligned.m16n8k16.row.col.f32.bf16.bf16.f32 "       \
                 "{%0,%1,%2,%3},{%4,%5,%6,%7},{%8,%9},{%0,%1,%2,%3};"         \
                 : "+f"(d[0]), "+f"(d[1]), "+f"(d[2]), "+f"(d[3])             \
                 : "r"(a[0]), "r"(a[1]), "r"(a[2]), "r"(a[3]),                \
                   "r"(b[0]), "r"(b[1]))

static __device__ __forceinline__ void load_stage(
    const bf16* __restrict__ Ahi, const bf16* __restrict__ Alo,
    const bf16* __restrict__ Whi, const bf16* __restrict__ Wlo,
    int M, int K, int bm, int bn, int k0, uint32_t sbase, int tid) {
#pragma unroll
    for (int i = 0; i < 8; i++) {
        int l = tid + 256 * i;          // 0..2047
        int plane = l >> 9;             // 0:Ahi 1:Alo 2:Whi 3:Wlo
        int c = l & 511;
        int row = c >> 2;
        int ch = c & 3;
        int sc = ch ^ ((row >> 1) & 3);          // swizzled 16B chunk
        uint32_t dst = sbase + plane * PLANE_B + row * 64 + sc * 16;
        if (plane < 2) {
            const bf16* base = plane ? Alo : Ahi;
            int gr = bm + row;
            int ok = gr < M;
            const bf16* g = base + (size_t)(ok ? gr : 0) * K + k0 + ch * 8;
            int sz = ok ? 16 : 0;
            asm volatile("cp.async.cg.shared.global [%0], [%1], 16, %2;\n"
                         :: "r"(dst), "l"(g), "r"(sz));
        } else {
            const bf16* base = (plane == 2) ? Whi : Wlo;
            const bf16* g = base + (size_t)(bn + row) * K + k0 + ch * 8;
            asm volatile("cp.async.cg.shared.global [%0], [%1], 16;\n"
                         :: "r"(dst), "l"(g));
        }
    }
}

__global__ __launch_bounds__(256, 2)
void gemm_split(const bf16* __restrict__ Ahi, const bf16* __restrict__ Alo,
                const bf16* __restrict__ Whi, const bf16* __restrict__ Wlo,
                float* __restrict__ C, int M, int N, int K, int kcps) {
    extern __shared__ __align__(128) char smem_raw[];
    uint32_t sbase = smem_u32(smem_raw);
    sbase = (sbase + 127u) & ~127u;

    const int tid = threadIdx.x;
    const int wid = tid >> 5;
    const int lane = tid & 31;
    const int warp_m = wid >> 2;
    const int warp_n = wid & 3;
    const int bm = blockIdx.y * BM;
    const int bn = blockIdx.x * BN;
    const int kbase = blockIdx.z * kcps * BK;
    C += (size_t)blockIdx.z * M * N;    // partial slice

    // per-lane ldmatrix addressing (byte offsets within a plane)
    const int ra = ((lane >> 3) & 1) * 8 + (lane & 7);
    const int cha = (lane >> 4) & 1;
    const int swza = (ra >> 1) & 3;
    const uint32_t a_row = (uint32_t)(warp_m * 64 + ra) * 64;
    const uint32_t ak0 = ((cha ^ swza) << 4);
    const uint32_t ak1 = (((2 + cha) ^ swza) << 4);

    const int rb = ((lane >> 4) & 1) * 8 + (lane & 7);
    const int chb = (lane >> 3) & 1;
    const int swzb = (rb >> 1) & 3;
    const uint32_t b_row = (uint32_t)(warp_n * 32 + rb) * 64;
    const uint32_t bk0 = ((chb ^ swzb) << 4);
    const uint32_t bk1 = (((2 + chb) ^ swzb) << 4);

    float acc[4][4][4];
#pragma unroll
    for (int mt = 0; mt < 4; mt++)
#pragma unroll
        for (int nt = 0; nt < 4; nt++)
#pragma unroll
            for (int e = 0; e < 4; e++) acc[mt][nt][e] = 0.f;

    load_stage(Ahi, Alo, Whi, Wlo, M, K, bm, bn, kbase, sbase, tid);
    asm volatile("cp.async.commit_group;\n");
    if (1 < kcps)
        load_stage(Ahi, Alo, Whi, Wlo, M, K, bm, bn, kbase + BK,
                   sbase + STAGE_B, tid);
    asm volatile("cp.async.commit_group;\n");

// load A hi/lo fragments for row-tile mt into buffer slot s
#define LDA_PAIR(s, mt, akk)                                                  \
    {                                                                         \
        uint32_t ad = pAhi + a_row + (mt) * 1024 + (akk);                     \
        LDM4(ahi[s][0], ahi[s][1], ahi[s][2], ahi[s][3], ad);                 \
        ad = pAlo + a_row + (mt) * 1024 + (akk);                              \
        LDM4(alo[s][0], alo[s][1], alo[s][2], alo[s][3], ad);                 \
    }
// interleaved pair: chain distance 8 per accumulator; per-acc term order
// unchanged (hi*bhi, hi*blo, lo*bhi)
#define PAIR_MMA(m0, m1)                                                      \
    {                                                                         \
        _Pragma("unroll") for (int nt = 0; nt < 4; nt++)                      \
            MMA_BF16(acc[m0][nt], ahi[0], bhi[nt]);                           \
        _Pragma("unroll") for (int nt = 0; nt < 4; nt++)                      \
            MMA_BF16(acc[m1][nt], ahi[1], bhi[nt]);                           \
        _Pragma("unroll") for (int nt = 0; nt < 4; nt++)                      \
            MMA_BF16(acc[m0][nt], ahi[0], blo[nt]);                           \
        _Pragma("unroll") for (int nt = 0; nt < 4; nt++)                      \
            MMA_BF16(acc[m1][nt], ahi[1], blo[nt]);                           \
        _Pragma("unroll") for (int nt = 0; nt < 4; nt++)                      \
            MMA_BF16(acc[m0][nt], alo[0], bhi[nt]);                           \
        _Pragma("unroll") for (int nt = 0; nt < 4; nt++)                      \
            MMA_BF16(acc[m1][nt], alo[1], bhi[nt]);                           \
    }

    for (int it = 0; it < kcps; it++) {
        asm volatile("cp.async.wait_group 1;\n");
        __syncthreads();

        const uint32_t sb = sbase + (it % NSTG) * STAGE_B;
        const uint32_t pAhi = sb;
        const uint32_t pAlo = sb + PLANE_B;
        const uint32_t pBhi = sb + 2 * PLANE_B;
        const uint32_t pBlo = sb + 3 * PLANE_B;

#pragma unroll
        for (int ks = 0; ks < 2; ks++) {
            const uint32_t akk = ks ? ak1 : ak0;
            const uint32_t bkk = ks ? bk1 : bk0;
            uint32_t bhi[4][2], blo[4][2];
#pragma unroll
            for (int q = 0; q < 2; q++) {
                uint32_t ad = pBhi + b_row + q * 16 * 64 + bkk;
                LDM4(bhi[2 * q][0], bhi[2 * q][1], bhi[2 * q + 1][0],
                     bhi[2 * q + 1][1], ad);
                ad = pBlo + b_row + q * 16 * 64 + bkk;
                LDM4(blo[2 * q][0], blo[2 * q][1], blo[2 * q + 1][0],
                     blo[2 * q + 1][1], ad);
            }
            uint32_t ahi[2][4], alo[2][4];
            LDA_PAIR(0, 0, akk)
            LDA_PAIR(1, 1, akk)
            PAIR_MMA(0, 1)
            if (ks == 0) {
                // prefetch overlapped with tensor work; commit exactly once/iter
                if (it + 2 < kcps)
                    load_stage(Ahi, Alo, Whi, Wlo, M, K, bm, bn,
                               kbase + (it + 2) * BK,
                               sbase + ((it + 2) % NSTG) * STAGE_B, tid);
                asm volatile("cp.async.commit_group;\n");
            }
            LDA_PAIR(0, 2, akk)
            LDA_PAIR(1, 3, akk)
            PAIR_MMA(2, 3)
        }
    }

    const int gid = lane >> 2;
    const int tig = lane & 3;
#pragma unroll
    for (int mt = 0; mt < 4; mt++) {
        int row0 = bm + warp_m * 64 + mt * 16 + gid;
        int row1 = row0 + 8;
#pragma unroll
        for (int nt = 0; nt < 4; nt++) {
            int col = bn + warp_n * 32 + nt * 8 + tig * 2;
            if (row0 < M)
                *(float2*)&C[(size_t)row0 * N + col] =
                    make_float2(acc[mt][nt][0], acc[mt][nt][1]);
            if (row1 < M)
                *(float2*)&C[(size_t)row1 * N + col] =
                    make_float2(acc[mt][nt][2], acc[mt][nt][3]);
        }
    }
}

// ---------------- elementwise gate kernels (float4 vectorized) ---------------
static __device__ __forceinline__ float sigmoidf_(float x) {
    return 1.f / (1.f + expf(-x));
}
static __device__ __forceinline__ void split_store(bf16* hhi, bf16* hlo,
                                                   int i4, float4 h) {
    bf16 h0 = __float2bfloat16(h.x), h1 = __float2bfloat16(h.y);
    bf16 h2 = __float2bfloat16(h.z), h3 = __float2bfloat16(h.w);
    ((__nv_bfloat162*)hhi)[i4 * 2]     = __nv_bfloat162(h0, h1);
    ((__nv_bfloat162*)hhi)[i4 * 2 + 1] = __nv_bfloat162(h2, h3);
    ((__nv_bfloat162*)hlo)[i4 * 2] = __nv_bfloat162(
        __float2bfloat16(h.x - __bfloat162float(h0)),
        __float2bfloat16(h.y - __bfloat162float(h1)));
    ((__nv_bfloat162*)hlo)[i4 * 2 + 1] = __nv_bfloat162(
        __float2bfloat16(h.z - __bfloat162float(h2)),
        __float2bfloat16(h.w - __bfloat162float(h3)));
}

__global__ void leaf_eltwise(const float* __restrict__ g,
                             const float* __restrict__ b,
                             float* __restrict__ c,
                             bf16* __restrict__ hhi, bf16* __restrict__ hlo,
                             int rows) {
    int i4 = blockIdx.x * blockDim.x + threadIdx.x;
    if (i4 >= rows * (MEMD / 4)) return;
    int row = i4 / (MEMD / 4);
    int m = (i4 - row * (MEMD / 4)) * 4;
    const float* gr = g + (size_t)row * 3 * MEMD;
    float4 gi = *(const float4*)&gr[m];
    float4 go = *(const float4*)&gr[MEMD + m];
    float4 gu = *(const float4*)&gr[2 * MEMD + m];
    float4 bi = *(const float4*)&b[MEMD + m];
    float4 bo = *(const float4*)&b[2 * MEMD + m];
    float4 bu = *(const float4*)&b[3 * MEMD + m];
    float4 cc, hh;
#define LEAF1(X)                                                              \
    {                                                                         \
        float iv = sigmoidf_(gi.X + bi.X), ov = sigmoidf_(go.X + bo.X);       \
        float uv = tanhf(gu.X + bu.X);                                        \
        cc.X = iv * uv; hh.X = ov * tanhf(cc.X);                              \
    }
    LEAF1(x) LEAF1(y) LEAF1(z) LEAF1(w)
#undef LEAF1
    ((float4*)c)[i4] = cc;
    split_store(hhi, hlo, i4, hh);
}

__global__ void node_eltwise(const float* __restrict__ g,
                             const float* __restrict__ b,
                             const float* __restrict__ c_prev,
                             float* __restrict__ c,
                             bf16* __restrict__ hhi, bf16* __restrict__ hlo,
                             float* __restrict__ hroot, int rows, int nsl) {
    int i4 = blockIdx.x * blockDim.x + threadIdx.x;
    if (i4 >= rows * (MEMD / 4)) return;
    int row = i4 / (MEMD / 4);
    int m = (i4 - row * (MEMD / 4)) * 4;
    const size_t sstride = (size_t)rows * 5 * MEMD;
    const float* gr = g + (size_t)row * 5 * MEMD;
    float4 gi = *(const float4*)&gr[m];
    float4 go = *(const float4*)&gr[MEMD + m];
    float4 gu = *(const float4*)&gr[2 * MEMD + m];
    float4 gfl = *(const float4*)&gr[3 * MEMD + m];
    float4 gfr = *(const float4*)&gr[4 * MEMD + m];
    for (int s = 1; s < nsl; s++) {
        const float* gs = gr + s * sstride;
        float4 t;
        t = *(const float4*)&gs[m];
        gi.x += t.x; gi.y += t.y; gi.z += t.z; gi.w += t.w;
        t = *(const float4*)&gs[MEMD + m];
        go.x += t.x; go.y += t.y; go.z += t.z; go.w += t.w;
        t = *(const float4*)&gs[2 * MEMD + m];
        gu.x += t.x; gu.y += t.y; gu.z += t.z; gu.w += t.w;
        t = *(const float4*)&gs[3 * MEMD + m];
        gfl.x += t.x; gfl.y += t.y; gfl.z += t.z; gfl.w += t.w;
        t = *(const float4*)&gs[4 * MEMD + m];
        gfr.x += t.x; gfr.y += t.y; gfr.z += t.z; gfr.w += t.w;
    }
    const float* cpr = c_prev + (size_t)row * 2 * MEMD;
    float4 bi = *(const float4*)&b[MEMD + m];
    float4 bo = *(const float4*)&b[2 * MEMD + m];
    float4 bu = *(const float4*)&b[3 * MEMD + m];
    float4 bf = *(const float4*)&b[m];
    float4 cl = *(const float4*)&cpr[m];
    float4 cr = *(const float4*)&cpr[MEMD + m];
    float4 cc, hh;
#define NODE1(X)                                                              \
    {                                                                         \
        float iv = sigmoidf_(gi.X + bi.X), ov = sigmoidf_(go.X + bo.X);       \
        float uv = tanhf(gu.X + bu.X);                                        \
        float fl = sigmoidf_(gfl.X + bf.X), fr = sigmoidf_(gfr.X + bf.X);     \
        cc.X = fmaf(iv, uv, fmaf(fl, cl.X, fr * cr.X));                       \
        hh.X = ov * tanhf(cc.X);                                              \
    }
    NODE1(x) NODE1(y) NODE1(z) NODE1(w)
#undef NODE1
    ((float4*)c)[i4] = cc;
    if (hroot)
        ((float4*)hroot)[i4] = hh;
    else
        split_store(hhi, hlo, i4, hh);
}

// ---------------- launch -----------------------------------------------------
extern "C" void kernel_launch(void* const* d_in, const int* in_sizes, int n_in,
                              void* d_out, int out_size) {
    const float* inputs  = (const float*)d_in[0];
    const float* w_fioux = (const float*)d_in[1];
    const float* b       = (const float*)d_in[2];
    const float* w_iouh  = (const float*)d_in[3];
    const float* w_fh    = (const float*)d_in[4];
    float* out = (float*)d_out;

    float *scr, *c0, *c1;
    bf16 *h0hi, *h0lo, *h1hi, *h1lo, *xhi, *xlo, *wxhi, *wxlo, *wchi, *wclo;
    cudaGetSymbolAddress((void**)&scr, g_scr);
    cudaGetSymbolAddress((void**)&c0, g_c0);
    cudaGetSymbolAddress((void**)&c1, g_c1);
    cudaGetSymbolAddress((void**)&h0hi, g_h0hi);
    cudaGetSymbolAddress((void**)&h0lo, g_h0lo);
    cudaGetSymbolAddress((void**)&h1hi, g_h1hi);
    cudaGetSymbolAddress((void**)&h1lo, g_h1lo);
    cudaGetSymbolAddress((void**)&xhi, g_xhi);
    cudaGetSymbolAddress((void**)&xlo, g_xlo);
    cudaGetSymbolAddress((void**)&wxhi, g_wxhi);
    cudaGetSymbolAddress((void**)&wxlo, g_wxlo);
    cudaGetSymbolAddress((void**)&wchi, g_wchi);
    cudaGetSymbolAddress((void**)&wclo, g_wclo);

    cudaFuncSetAttribute(gemm_split, cudaFuncAttributeMaxDynamicSharedMemorySize,
                         SMEM_DYN);

    const int rowsL = BB * NL;  // 16384

    {
        int n0 = rowsL * INDIM / 4;
        int n1 = 3 * MEMD * INDIM / 4;
        int n2 = 3 * MEMD * 2 * MEMD / 4;
        int n3 = 2 * MEMD * 2 * MEMD / 4;
        size_t off = (size_t)3 * MEMD * 2 * MEMD;
        int tot = n0 + n1 + n2 + n3;
        split_all<<<(tot + 255) / 256, 256>>>(
            inputs, xhi, xlo, n0,
            w_fioux + (size_t)MEMD * INDIM, wxhi, wxlo, n1,
            w_iouh, wchi, wclo, n2,
            w_fh, wchi + off, wclo + off, n3);
    }

    gemm_split<<<dim3(3 * MEMD / BN, rowsL / BM, 1), 256, SMEM_DYN>>>(
        xhi, xlo, wxhi, wxlo, scr, rowsL, 3 * MEMD, INDIM, INDIM / BK);
    leaf_eltwise<<<(rowsL * MEMD / 4 + 255) / 256, 256>>>(scr, b, c0, h0hi,
                                                          h0lo, rowsL);

    float *cp = c0, *cn = c1;
    bf16 *hpi = h0hi, *hpl = h0lo, *hni = h1hi, *hnl = h1lo;
    for (int n = NL / 2; n >= 1; n >>= 1) {
        int rows = BB * n;
        int ks = rows >= 1024 ? 1
               : rows == 512 ? 2
               : rows == 256 ? 4
               : rows == 128 ? 8 : 16;
        int kcps = (2 * MEMD / BK) / ks;   // 64 / ks
        int gy = (rows + BM - 1) / BM;
        gemm_split<<<dim3(5 * MEMD / BN, gy, ks), 256, SMEM_DYN>>>(
            hpi, hpl, wchi, wclo, scr, rows, 5 * MEMD, 2 * MEMD, kcps);
        node_eltwise<<<(rows * MEMD / 4 + 255) / 256, 256>>>(
            scr, b, cp, cn, hni, hnl, (n == 1) ? out : (float*)nullptr, rows, ks);
        float* tc = cp; cp = cn; cn = tc;
        bf16* t;
        t = hpi; hpi = hni; hni = t;
        t = hpl; hpl = hnl; hnl = t;
    }
}